// round 14
// baseline (speedup 1.0000x reference)
#include <cuda_runtime.h>
#include <cuda_bf16.h>
#include <math.h>

#define NB 4
#define NM 32
#define CT 282
#define CTP 284             // padded row stride for d_At (float4-safe tail)
#define CT2 (CT*CT)
#define KTOT 24576          // 2 * 12288 floats per Gram row
#define SEG 256
#define NSEG 96
#define EPSR 1e-3f
#define NTH 768             // k_main threads
#define NW  24              // warps in k_main

#define SXP2_N 3720         // down-aliased pyramid complex elements per (b,m)
#define SC_N   3720         // C-table complex elements per (b,m)
// sXp2 + sC (float2) + sS (1364 f) + sU (1536 f)
#define SMEM_MAIN ((SXP2_N + SC_N) * 8 + (1364 + 1536) * 4)   // 71120 bytes

// per-level constants
__constant__ int c_h[5]     = {2,4,8,16,32};
__constant__ int c_cnt[5]   = {192,48,24,12,6};
__constant__ int c_cbase[6] = {0,192,240,264,276,282};
__constant__ int c_OffC[5]  = {0,768,1536,3072,6144};   // complex offset of level block in Zh
__constant__ int c_LB2[5]   = {0,0,192,672,1680};       // compact pyramid base per level
__constant__ int c_PS2[5]   = {0,4,20,84,340};          // compact per-channel pyramid size
__constant__ int c_LO[5]    = {0,4,20,84,340};          // offset of level-l slice inside a channel stack

// phase-3 warp-item schedule (46 items over 24 warps, 2 rounds, -1 = idle)
__constant__ int c_perm[48] = {
    0,1,2,3,4,5,6,7,8,9,10,11,12,13,14,15,16,17,18,19,20,21,22,23,
    36,37,38,39,40,41,42,43,44,45,-1,-1,30,31,32,33,34,35,24,25,26,27,28,29
};

// prepA upper-triangular block pairs (9x9 -> 45)
__constant__ int c_pbi[45] = {0,0,0,0,0,0,0,0,0, 1,1,1,1,1,1,1,1, 2,2,2,2,2,2,2,
                              3,3,3,3,3,3, 4,4,4,4,4, 5,5,5,5, 6,6,6, 7,7, 8};
__constant__ int c_pbj[45] = {0,1,2,3,4,5,6,7,8, 1,2,3,4,5,6,7,8, 2,3,4,5,6,7,8,
                              3,4,5,6,7,8, 4,5,6,7,8, 5,6,7,8, 6,7,8, 7,8, 8};

// dft job table: 42 jobs
__constant__ int jb_l[42]  = {0,0,0,0,0,0, 1,1,1,1,1,1, 2,2,2,2,2,2,2,2,2,2,2,2,
                              3,3,3,3,3,3,3,3,3,3,3,3, 4,4,4,4,4,4};
__constant__ int jb_c0[42] = {0,32,64,96,128,160, 0,8,16,24,32,40,
                              0,2,4,6,8,10,12,14,16,18,20,22,
                              0,1,2,3,4,5,6,7,8,9,10,11, 0,1,2,3,4,5};
__constant__ int jb_n[42]  = {32,32,32,32,32,32, 8,8,8,8,8,8, 2,2,2,2,2,2,2,2,2,2,2,2,
                              1,1,1,1,1,1,1,1,1,1,1,1, 1,1,1,1,1,1};

// scratch (device globals; no allocation)
__device__ __align__(16) float d_At[NM*CT*CTP];        // At[m][c][d] (stride CTP)
__device__ float  d_Spyr[NM*1364];                     // alias pyramid of s per mode
__device__ __align__(16) float2 d_Zh[NB*12288];        // per-level DFTs of z
__device__ __align__(16) float  d_V [(size_t)NB*33*KTOT]; // Gram rows (0..31 = U-hat, 32 = w-hat)
__device__ float  d_G [NB*1089];                       // Gram accumulators (atomic)

struct InPtrs { const float* z[5]; const float* w[5]; };

// ----------------------------------------------------------- f32x2 helpers
__device__ __forceinline__ unsigned long long pack2(float a){
    unsigned long long r;
    asm("mov.b64 %0, {%1, %1};" : "=l"(r) : "f"(a));
    return r;
}
__device__ __forceinline__ void ffma2(unsigned long long &d, unsigned long long a, unsigned long long b){
    asm("fma.rn.f32x2 %0, %1, %2, %0;" : "+l"(d) : "l"(a), "l"(b));
}
__device__ __forceinline__ void fadd2(unsigned long long &d, unsigned long long a){
    asm("add.rn.f32x2 %0, %1, %0;" : "+l"(d) : "l"(a));
}
__device__ __forceinline__ void fmul2(unsigned long long &d, unsigned long long a){
    asm("mul.rn.f32x2 %0, %1, %0;" : "+l"(d) : "l"(a));
}
__device__ __forceinline__ float2 unpack2(unsigned long long v){
    float2 r;
    asm("mov.b64 {%0, %1}, %2;" : "=f"(r.x), "=f"(r.y) : "l"(v));
    return r;
}

// 4d x 1k accumulate (ac0..ac3) with broadcast A float4 and one X value
#define ACC4(av, x) do { \
    ffma2(ac0, pack2((av).x), (x)); \
    ffma2(ac1, pack2((av).y), (x)); \
    ffma2(ac2, pack2((av).z), (x)); \
    ffma2(ac3, pack2((av).w), (x)); \
} while(0)

// 4d x 4k accumulate into ac[16] (d-major), X = 4 consecutive complex
#define ACC16A(av, x01, x23) do { \
    unsigned long long A0=pack2((av).x), A1=pack2((av).y); \
    unsigned long long A2=pack2((av).z), A3=pack2((av).w); \
    ffma2(ac[0], A0,(x01).x); ffma2(ac[1], A0,(x01).y); ffma2(ac[2], A0,(x23).x); ffma2(ac[3], A0,(x23).y); \
    ffma2(ac[4], A1,(x01).x); ffma2(ac[5], A1,(x01).y); ffma2(ac[6], A1,(x23).x); ffma2(ac[7], A1,(x23).y); \
    ffma2(ac[8], A2,(x01).x); ffma2(ac[9], A2,(x01).y); ffma2(ac[10],A2,(x23).x); ffma2(ac[11],A2,(x23).y); \
    ffma2(ac[12],A3,(x01).x); ffma2(ac[13],A3,(x01).y); ffma2(ac[14],A3,(x23).x); ffma2(ac[15],A3,(x23).y); \
} while(0)

// ============= fused preprocessing: prepA (blocks 0..1439), spyr (1440..1471), dft (1472..1807)
__global__ void __launch_bounds__(256) k_prep(const float* __restrict__ L,
                                              const float* __restrict__ lam,
                                              InPtrs P){
    __shared__ float sh[3136];
    int bx = blockIdx.x;
    int tid = threadIdx.x;

    if (bx < 1440){
        // ---------------- At = L^T - L, pair-tiled (32x32 pair per block)
        float (*Ta)[33] = (float(*)[33])sh;
        float (*Tb)[33] = (float(*)[33])(sh + 1056);
        int m = bx / 45, p = bx - m*45;
        int i0 = c_pbi[p]*32, j0 = c_pbj[p]*32;
        int tx = tid & 31, ty0 = tid >> 5;
        const float* Lm = L + (size_t)m*CT2;
        #pragma unroll
        for (int rr=0; rr<4; ++rr){
            int ty = ty0 + rr*8;
            int r = i0+ty, c = j0+tx;
            Ta[ty][tx] = (r<CT && c<CT) ? Lm[r*CT + c] : 0.f;
            r = j0+ty; c = i0+tx;
            Tb[ty][tx] = (r<CT && c<CT) ? Lm[r*CT + c] : 0.f;
        }
        __syncthreads();
        #pragma unroll
        for (int rr=0; rr<4; ++rr){
            int ty = ty0 + rr*8;
            if (i0+ty<CT && j0+tx<CT)
                d_At[((size_t)m*CT + i0+ty)*CTP + j0+tx] = Ta[ty][tx] - Tb[tx][ty];
            if (j0+ty<CT && i0+tx<CT)
                d_At[((size_t)m*CT + j0+ty)*CTP + i0+tx] = Tb[ty][tx] - Ta[tx][ty];
        }
    } else if (bx < 1472){
        // ---------------- s pyramid + zero d_G
        float* sA = sh;           // 1024
        float* sB = sh + 1024;    // 256
        int m = bx - 1440;
        int gidx = m*256 + tid;
        if (gidx < NB*1089) d_G[gidx] = 0.f;
        const float* lm = lam + m*1024;
        for (int t=tid; t<1024; t+=256){
            int p = t>>5, q = t&31;
            float v = lm[t] - lm[(((32-p)&31)<<5) + ((32-q)&31)];
            sA[t] = v;
            d_Spyr[m*1364 + 340 + t] = v;
        }
        float* src = sA; float* dst = sB;
        int hs = 32;
        for (int k=0; k<4; ++k){
            __syncthreads();
            int hn = hs>>1;
            int off = c_LO[3-k];        // 84,20,4,0
            for (int t=tid; t<hn*hn; t+=256){
                int p = t/hn, q = t-p*hn;
                float v = src[p*hs+q] + src[(p+hn)*hs+q]
                        + src[p*hs+q+hn] + src[(p+hn)*hs+q+hn];
                dst[t] = v;
                d_Spyr[m*1364 + off + t] = v;
            }
            float* tmp = src; src = dst; dst = tmp;
            hs = hn;
        }
    } else {
        // ---------------- batched small 2D DFTs of z (and w -> V row 32)
        float* sIn = sh;            // 1024
        float* tRe = sh + 1024;     // 1024
        float* tIm = sh + 2048;     // 1024
        float2* tw = (float2*)(sh + 3072);  // 32
        int idx = bx - 1472;
        int j = idx % 42;
        int t2 = idx / 42;
        int b = t2 & 3, isw = t2 >> 2;
        int l = jb_l[j];
        int h = c_h[l], hm = h-1;
        int lh = 31 - __clz(h);
        int lh2 = 2*lh;
        int h2 = h*h;
        int c0 = jb_c0[j], nch = jb_n[j];
        int npts = nch*h2;
        const float* in = (isw ? P.w[l] : P.z[l]) + (size_t)(b*c_cnt[l] + c0)*h2;
        if (tid < h){
            float sn, cn; __sincosf(-6.283185307179586f*(float)tid/(float)h, &sn, &cn);
            tw[tid] = make_float2(cn, sn);
        }
        for (int t=tid; t<npts; t+=256) sIn[t] = in[t];
        __syncthreads();
        for (int t=tid; t<npts; t+=256){
            int ch = t>>lh2;
            int pt = t & (h2-1);
            int p = pt>>lh, x = pt&hm;
            const float* base = sIn + (ch<<lh2) + x;
            float ar=0.f, ai=0.f;
            for (int y=0; y<h; ++y){
                float2 e = tw[(p*y)&hm];
                float v = base[y<<lh];
                ar += v*e.x; ai += v*e.y;
            }
            tRe[t]=ar; tIm[t]=ai;
        }
        __syncthreads();
        float inv = 1.0f/(float)h;
        float* vrow = d_V + ((size_t)(b*33+32))*KTOT;
        for (int t=tid; t<npts; t+=256){
            int ch = t>>lh2;
            int pt = t & (h2-1);
            int p = pt>>lh, q = pt&hm;
            const float* bR = tRe + (ch<<lh2) + (p<<lh);
            const float* bI = tIm + (ch<<lh2) + (p<<lh);
            float ar=0.f, ai=0.f;
            for (int x=0; x<h; ++x){
                float2 e = tw[(q*x)&hm];
                float re = bR[x], im = bI[x];
                ar += re*e.x - im*e.y;
                ai += re*e.y + im*e.x;
            }
            int kk = c_OffC[l] + (c0<<lh2) + t;
            if (!isw){
                d_Zh[b*12288 + kk] = make_float2(ar, ai);
            } else {
                vrow[2*kk  ] =  ai*inv;
                vrow[2*kk+1] = -ar*inv;
            }
        }
    }
}

// 4-point downward alias within compact pyramid (smem)
__device__ __forceinline__ void alias_down(float2* __restrict__ sXp2,
                                           int lc, int lt, int ch, int pt){
    int ht = c_h[lt], hsrc = ht*2;
    int p = pt / ht, q = pt - p*ht;
    float2* base = sXp2 + c_LB2[lc] + ch*c_PS2[lc];
    const float2* src = base + c_LO[lt+1];
    float2 a0=src[p*hsrc+q],        a1=src[(p+ht)*hsrc+q];
    float2 a2=src[p*hsrc+q+ht],     a3=src[(p+ht)*hsrc+q+ht];
    base[c_LO[lt]+pt] = make_float2(a0.x+a1.x+a2.x+a3.x, a0.y+a1.y+a2.y+a3.y);
}

// ====================== fused per-(b,m) vector-field kernel ======================
__global__ void __launch_bounds__(NTH) k_main(){
    extern __shared__ float smraw[];
    float2* sXp2 = (float2*)smraw;             // [SXP2_N]
    float2* sC   = sXp2 + SXP2_N;              // [SC_N]
    float*  sS   = (float*)(sC + SC_N);        // [1364]
    float*  sU   = sS + 1364;                  // [1536] level-0 accumulators
    int m = blockIdx.x, b = blockIdx.y;
    int tid = threadIdx.x;
    int wid = tid >> 5, lane = tid & 31;

    for (int t=tid; t<1364; t+=NTH) sS[t] = d_Spyr[m*1364 + t];
    for (int t=tid; t<1536; t+=NTH) sU[t] = 0.f;
    for (int t=tid; t<720;  t+=NTH) ((float*)sC)[t] = 0.f;   // ls=0 C region (atomic)
    __syncthreads();

    const float2* Zb = d_Zh + b*12288;
    const float*  Atm = d_At + (size_t)m*CT*CTP;

    // ---- phase 1A: top stored slice per channel (4-pt alias from global Z x S)
    for (int t=tid; t<2880; t+=NTH){
        int lc, ch, pt;
        if (t<192){lc=1; ch=t>>2; pt=t&3;}
        else if (t<576){lc=2; int u=t-192; ch=u>>4; pt=u&15;}
        else if (t<1344){lc=3; int u=t-576; ch=u>>6; pt=u&63;}
        else {lc=4; int u=t-1344; ch=u>>8; pt=u&255;}
        int ht = c_h[lc-1], hs = ht*2;
        int p = pt / ht, q = pt - p*ht;
        const float* Sl = sS + c_LO[lc];
        const float2* Zc = Zb + c_OffC[lc] + ch*hs*hs;
        float ar=0.f, ai=0.f;
        #pragma unroll
        for (int i=0;i<2;++i){
            #pragma unroll
            for (int jj=0;jj<2;++jj){
                int idx = (p+i*ht)*hs + (q+jj*ht);
                float s = Sl[idx];
                float2 z = Zc[idx];
                ar += s*z.x; ai += s*z.y;
            }
        }
        sXp2[c_LB2[lc] + ch*c_PS2[lc] + c_LO[lc-1] + pt] = make_float2(ar, ai);
    }
    __syncthreads();

    // ---- phase 1B: downward aliasing within smem (3 rounds)
    for (int t=tid; t<672; t+=NTH){
        if (t<96)       alias_down(sXp2, 2, 0, t>>2, t&3);
        else if (t<288){int u=t-96;  alias_down(sXp2, 3, 1, u>>4, u&15);}
        else           {int u=t-288; alias_down(sXp2, 4, 2, u>>6, u&63);}
    }
    __syncthreads();
    for (int t=tid; t<144; t+=NTH){
        if (t<48)      alias_down(sXp2, 3, 0, t>>2, t&3);
        else          {int u=t-48; alias_down(sXp2, 4, 1, u>>4, u&15);}
    }
    __syncthreads();
    for (int t=tid; t<24; t+=NTH) alias_down(sXp2, 4, 0, t>>2, t&3);
    __syncthreads();

    // ---- phase 2: C table, warp-cooperative (63 warp-items)
    for (int it = wid; it < 63; it += NW){
        if (it < 12){
            // ls0: lane = d (32 per group, 3 groups: 0..95, valid <90), 4 residues in regs
            int g = it >> 2, cc = it & 3;
            int di = g*32 + lane;
            bool ok = di < 90;
            int diL = ok ? di : 89;
            int clo = cc*48, chi = clo+48;
            unsigned long long a0=0ull,a1=0ull,a2=0ull,a3=0ull;
            const float* ap = Atm + (size_t)clo*CTP + 192 + diL;
            const ulonglong2* zp = (const ulonglong2*)((const unsigned long long*)Zb + clo*4);
            for (int c=clo; c<chi; ++c){
                unsigned long long av = pack2(__ldg(ap));
                ulonglong2 z01 = zp[0];
                ulonglong2 z23 = zp[1];
                ffma2(a0,av,z01.x); ffma2(a1,av,z01.y);
                ffma2(a2,av,z23.x); ffma2(a3,av,z23.y);
                ap += CTP; zp += 2;
            }
            if (ok){
                float* f = (float*)sC + di*8;
                float2 v;
                v=unpack2(a0); atomicAdd(f+0,v.x); atomicAdd(f+1,v.y);
                v=unpack2(a1); atomicAdd(f+2,v.x); atomicAdd(f+3,v.y);
                v=unpack2(a2); atomicAdd(f+4,v.x); atomicAdd(f+5,v.y);
                v=unpack2(a3); atomicAdd(f+6,v.x); atomicAdd(f+7,v.y);
            }
        } else if (it < 33){                 // ls1: 21 items, 2 di x 16 r
            int ii = it - 12;
            int di = ii*2 + (lane>>4);       // 0..41
            int r  = lane & 15;
            unsigned long long acc = 0ull;
            const float* ap = Atm + (size_t)192*CTP + 240 + di;
            const unsigned long long* zp = (const unsigned long long*)(Zb + 768) + r;
            for (int c=0;c<48;++c){
                ffma2(acc, pack2(__ldg(ap)), zp[(size_t)c*16]);
                ap += CTP;
            }
            ((unsigned long long*)sC)[360 + di*16 + r] = acc;
        } else if (it < 51){                 // ls2: 18 items, 1 di x 64 r (2/lane)
            int di = it - 33;
            int r0 = lane*2;
            unsigned long long a0=0ull, a1=0ull;
            const float* ap = Atm + (size_t)240*CTP + 264 + di;
            const ulonglong2* zp = (const ulonglong2*)(Zb + 1536 + r0);
            for (int c=0;c<24;++c){
                unsigned long long av = pack2(__ldg(ap));
                ulonglong2 z = zp[(size_t)c*32];
                ffma2(a0, av, z.x); ffma2(a1, av, z.y);
                ap += CTP;
            }
            unsigned long long* Cu = (unsigned long long*)sC + 1032 + di*64 + r0;
            Cu[0]=a0; Cu[1]=a1;
        } else {                             // ls3: 12 items, (di, kt), 4 r/lane
            int u = it - 51;
            int di = u >> 1, kt = u & 1;
            int r0 = kt*128 + lane*4;
            unsigned long long a0=0ull,a1=0ull,a2=0ull,a3=0ull;
            const float* ap = Atm + (size_t)264*CTP + 276 + di;
            const ulonglong2* zp = (const ulonglong2*)(Zb + 3072 + r0);
            for (int c=0;c<12;++c){
                unsigned long long av = pack2(__ldg(ap));
                ulonglong2 z01 = zp[(size_t)c*128];
                ulonglong2 z23 = zp[(size_t)c*128 + 1];
                ffma2(a0,av,z01.x); ffma2(a1,av,z01.y);
                ffma2(a2,av,z23.x); ffma2(a3,av,z23.y);
                ap += CTP;
            }
            unsigned long long* Cu = (unsigned long long*)sC + 2184 + di*256 + r0;
            Cu[0]=a0; Cu[1]=a1; Cu[2]=a2; Cu[3]=a3;
        }
    }
    __syncthreads();

    // ---- phase 3: mixing, warp-cooperative (46 warp-items, 2-round snake schedule)
    float* vbase = d_V + ((size_t)(b*33+m))*KTOT;
    const unsigned long long* Cb0 = (const unsigned long long*)sC;
    for (int s = wid; s < 48; s += NW){
        int it = c_perm[s];
        if (it < 0) continue;

        if (it < 12){
            // l0: lane = d (32 per group, 6 groups), 4 k in regs; 2 channel-chunks
            int g = it >> 1, chunk = it & 1;
            int d = g*32 + lane;
            unsigned long long ac0=0ull,ac1=0ull,ac2=0ull,ac3=0ull;
            int clo = chunk ? 141 : 0;
            int ce  = chunk ? 192 : 141;
            {
                const float* ap = Atm + (size_t)clo*CTP + d;
                const ulonglong2* zp = (const ulonglong2*)((const unsigned long long*)Zb + clo*4);
                for (int c=clo; c<ce; ++c){
                    unsigned long long av = pack2(__ldg(ap));
                    ulonglong2 x01 = zp[0];
                    ulonglong2 x23 = zp[1];
                    ffma2(ac0,av,x01.x); ffma2(ac1,av,x01.y);
                    ffma2(ac2,av,x23.x); ffma2(ac3,av,x23.y);
                    ap += CTP; zp += 2;
                }
                fmul2(ac0, pack2(sS[0])); fmul2(ac1, pack2(sS[1]));
                fmul2(ac2, pack2(sS[2])); fmul2(ac3, pack2(sS[3]));
            }
            if (chunk){
                for (int lc=1; lc<5; ++lc){
                    int cb=c_cbase[lc], ce2=c_cbase[lc+1];
                    int ps2 = c_PS2[lc] >> 1;    // stride in ulonglong2 units
                    const ulonglong2* xp = (const ulonglong2*)(sXp2 + c_LB2[lc]);
                    const float* ap = Atm + (size_t)cb*CTP + d;
                    for (int c=cb;c<ce2;++c){
                        unsigned long long av = pack2(__ldg(ap));
                        ulonglong2 x01 = xp[0];
                        ulonglong2 x23 = xp[1];
                        ffma2(ac0,av,x01.x); ffma2(ac1,av,x01.y);
                        ffma2(ac2,av,x23.x); ffma2(ac3,av,x23.y);
                        ap += CTP; xp += ps2;
                    }
                }
            }
            float* u = sU + d*8;
            float2 v;
            v=unpack2(ac0); atomicAdd(u+0,v.x); atomicAdd(u+1,v.y);
            v=unpack2(ac1); atomicAdd(u+2,v.x); atomicAdd(u+3,v.y);
            v=unpack2(ac2); atomicAdd(u+4,v.x); atomicAdd(u+5,v.y);
            v=unpack2(ac3); atomicAdd(u+6,v.x); atomicAdd(u+7,v.y);
        } else if (it < 18){
            // l1: 8 d x 16 k; lanes = (dl in 2, k in 16)
            int ii = it - 12;
            int dl = lane >> 4;
            int k  = lane & 15;
            int d0 = 192 + ii*8 + dl*4;
            int p = k>>2, q = k&3;
            int r = (p&1)*2 + (q&1);
            unsigned long long ac0 = Cb0[(d0-192)*4 + r];
            unsigned long long ac1 = Cb0[(d0-191)*4 + r];
            unsigned long long ac2 = Cb0[(d0-190)*4 + r];
            unsigned long long ac3 = Cb0[(d0-189)*4 + r];
            {
                const float* ap = Atm + (size_t)192*CTP + d0;
                const unsigned long long* zp = (const unsigned long long*)(Zb + 768) + k;
                for (int c=0;c<48;++c){
                    float4 av = __ldg((const float4*)ap);
                    unsigned long long x = zp[(size_t)c*16];
                    ACC4(av, x);
                    ap += CTP;
                }
                unsigned long long s2 = pack2(sS[4+k]);
                fmul2(ac0,s2); fmul2(ac1,s2); fmul2(ac2,s2); fmul2(ac3,s2);
            }
            for (int lc=2; lc<5; ++lc){
                int cb=c_cbase[lc], ce2=c_cbase[lc+1];
                int ps=c_PS2[lc];
                const unsigned long long* xp = (const unsigned long long*)(sXp2 + c_LB2[lc]) + 4 + k;
                const float* ap = Atm + (size_t)cb*CTP + d0;
                for (int c=cb;c<ce2;++c){
                    float4 av = __ldg((const float4*)ap);
                    unsigned long long x = *xp;
                    ACC4(av, x);
                    ap += CTP; xp += ps;
                }
            }
            const float sc = 4.0f/1024.0f;
            float* vp = vbase + 2*(768 + (d0-192)*16 + k);
            float2 v;
            v=unpack2(ac0); vp[0]=sc*v.x;  vp[1]=sc*v.y;
            v=unpack2(ac1); vp[32]=sc*v.x; vp[33]=sc*v.y;
            v=unpack2(ac2); vp[64]=sc*v.x; vp[65]=sc*v.y;
            v=unpack2(ac3); vp[96]=sc*v.x; vp[97]=sc*v.y;
        } else if (it < 24){
            // l2: 4 d x 64 k; lanes = 2 k each
            int dg = it - 18;
            int d0 = 240 + dg*4;
            int k0 = lane*2;
            unsigned long long ac[8];
            #pragma unroll
            for (int j=0;j<2;++j){
                int k = k0+j;
                int p=k>>3, q=k&7;
                int r0=(p&1)*2+(q&1), r1=(p&3)*4+(q&3);
                #pragma unroll
                for (int dj=0;dj<4;++dj){
                    unsigned long long a = Cb0[(d0-192+dj)*4 + r0];
                    fadd2(a, Cb0[360 + (d0-240+dj)*16 + r1]);
                    ac[dj*2+j] = a;
                }
            }
            {
                const float* ap = Atm + (size_t)240*CTP + d0;
                const ulonglong2* zp = (const ulonglong2*)(Zb + 1536 + k0);
                for (int c=0;c<24;++c){
                    float4 av = __ldg((const float4*)ap);
                    ulonglong2 x = zp[(size_t)c*32];
                    unsigned long long A0=pack2(av.x),A1=pack2(av.y),A2=pack2(av.z),A3=pack2(av.w);
                    ffma2(ac[0],A0,x.x); ffma2(ac[1],A0,x.y);
                    ffma2(ac[2],A1,x.x); ffma2(ac[3],A1,x.y);
                    ffma2(ac[4],A2,x.x); ffma2(ac[5],A2,x.y);
                    ffma2(ac[6],A3,x.x); ffma2(ac[7],A3,x.y);
                    ap += CTP;
                }
                unsigned long long s0 = pack2(sS[20+k0]);
                unsigned long long s1 = pack2(sS[21+k0]);
                fmul2(ac[0],s0); fmul2(ac[1],s1);
                fmul2(ac[2],s0); fmul2(ac[3],s1);
                fmul2(ac[4],s0); fmul2(ac[5],s1);
                fmul2(ac[6],s0); fmul2(ac[7],s1);
            }
            for (int lc=3; lc<5; ++lc){
                int cb=c_cbase[lc], ce2=c_cbase[lc+1];
                int ps2 = c_PS2[lc]>>1;
                const ulonglong2* xp = (const ulonglong2*)(sXp2 + c_LB2[lc] + 20 + k0);
                const float* ap = Atm + (size_t)cb*CTP + d0;
                for (int c=cb;c<ce2;++c){
                    float4 av = __ldg((const float4*)ap);
                    ulonglong2 x = *xp;
                    unsigned long long A0=pack2(av.x),A1=pack2(av.y),A2=pack2(av.z),A3=pack2(av.w);
                    ffma2(ac[0],A0,x.x); ffma2(ac[1],A0,x.y);
                    ffma2(ac[2],A1,x.x); ffma2(ac[3],A1,x.y);
                    ffma2(ac[4],A2,x.x); ffma2(ac[5],A2,x.y);
                    ffma2(ac[6],A3,x.x); ffma2(ac[7],A3,x.y);
                    ap += CTP; xp += ps2;
                }
            }
            const float sc = 8.0f/1024.0f;
            #pragma unroll
            for (int dj=0;dj<4;++dj){
                float* vp = vbase + 2*(1536 + (d0-240+dj)*64 + k0);
                float2 va=unpack2(ac[dj*2]), vb=unpack2(ac[dj*2+1]);
                *(float4*)vp = make_float4(sc*va.x, sc*va.y, sc*vb.x, sc*vb.y);
            }
        } else if (it < 30){
            // l3: 4 d x 128 k; lanes = 4 k each
            int u = it - 24;
            int dg = u >> 1, kt = u & 1;
            int d0 = 264 + dg*4;
            int k0 = kt*128 + lane*4;
            unsigned long long ac[16];
            int p = k0 >> 4, q0 = k0 & 15;
            #pragma unroll
            for (int j=0;j<4;++j){
                int q = q0 + j;
                int r0=(p&1)*2+(q&1), r1=(p&3)*4+(q&3), r2=(p&7)*8+(q&7);
                #pragma unroll
                for (int dj=0;dj<4;++dj){
                    unsigned long long a = Cb0[(d0-192+dj)*4 + r0];
                    fadd2(a, Cb0[360 + (d0-240+dj)*16 + r1]);
                    fadd2(a, Cb0[1032 + (d0-264+dj)*64 + r2]);
                    ac[dj*4+j] = a;
                }
            }
            {
                const float* ap = Atm + (size_t)264*CTP + d0;
                const ulonglong2* zp = (const ulonglong2*)(Zb + 3072 + k0);
                for (int c=0;c<12;++c){
                    float4 av = __ldg((const float4*)ap);
                    ulonglong2 x01 = zp[(size_t)c*128];
                    ulonglong2 x23 = zp[(size_t)c*128 + 1];
                    ACC16A(av, x01, x23);
                    ap += CTP;
                }
                #pragma unroll
                for (int j=0;j<4;++j){
                    unsigned long long s2 = pack2(sS[84 + k0 + j]);
                    fmul2(ac[j],s2); fmul2(ac[4+j],s2); fmul2(ac[8+j],s2); fmul2(ac[12+j],s2);
                }
            }
            {
                const ulonglong2* xp = (const ulonglong2*)(sXp2 + 1680 + 84 + k0);
                const float* ap = Atm + (size_t)276*CTP + d0;
                for (int c=0;c<6;++c){
                    float4 av = __ldg((const float4*)ap);
                    ulonglong2 x01 = xp[0];
                    ulonglong2 x23 = xp[1];
                    ACC16A(av, x01, x23);
                    ap += CTP; xp += 170;
                }
            }
            const float sc = 16.0f/1024.0f;
            #pragma unroll
            for (int dj=0;dj<4;++dj){
                float* vp = vbase + 2*(3072 + (d0-264+dj)*256 + k0);
                float2 v0=unpack2(ac[dj*4+0]), v1=unpack2(ac[dj*4+1]);
                float2 v2=unpack2(ac[dj*4+2]), v3=unpack2(ac[dj*4+3]);
                *(float4*)vp     = make_float4(sc*v0.x, sc*v0.y, sc*v1.x, sc*v1.y);
                *(float4*)(vp+4) = make_float4(sc*v2.x, sc*v2.y, sc*v3.x, sc*v3.y);
            }
        } else {
            // l4: up to 4 d x 128 k; lanes = 4 k each
            int u = it - 30;
            int dg = u >> 3, kt = u & 7;
            int d0 = 276 + dg*4;
            int dcnt = 282 - d0; if (dcnt>4) dcnt=4;
            int k0 = kt*128 + lane*4;
            unsigned long long ac[16];
            int p = k0 >> 5, q0 = k0 & 31;
            #pragma unroll
            for (int j=0;j<4;++j){
                int q = q0 + j;
                int r0=(p&1)*2+(q&1), r1=(p&3)*4+(q&3);
                int r2=(p&7)*8+(q&7), r3=(p&15)*16+(q&15);
                #pragma unroll
                for (int dj=0;dj<4;++dj){
                    unsigned long long a = Cb0[(d0-192+dj)*4 + r0];
                    fadd2(a, Cb0[360 + (d0-240+dj)*16 + r1]);
                    fadd2(a, Cb0[1032 + (d0-264+dj)*64 + r2]);
                    fadd2(a, Cb0[2184 + (d0-276+dj)*256 + r3]);
                    ac[dj*4+j] = a;
                }
            }
            {
                const float* ap = Atm + (size_t)276*CTP + d0;
                const ulonglong2* zp = (const ulonglong2*)(Zb + 6144 + k0);
                for (int c=0;c<6;++c){
                    float4 av = __ldg((const float4*)ap);
                    ulonglong2 x01 = zp[(size_t)c*512];
                    ulonglong2 x23 = zp[(size_t)c*512 + 1];
                    ACC16A(av, x01, x23);
                    ap += CTP;
                }
                #pragma unroll
                for (int j=0;j<4;++j){
                    unsigned long long s2 = pack2(sS[340 + k0 + j]);
                    fmul2(ac[j],s2); fmul2(ac[4+j],s2); fmul2(ac[8+j],s2); fmul2(ac[12+j],s2);
                }
            }
            const float sc = 32.0f/1024.0f;
            for (int dj=0;dj<dcnt;++dj){
                float* vp = vbase + 2*(6144 + (d0-276+dj)*1024 + k0);
                float2 v0=unpack2(ac[dj*4+0]), v1=unpack2(ac[dj*4+1]);
                float2 v2=unpack2(ac[dj*4+2]), v3=unpack2(ac[dj*4+3]);
                *(float4*)vp     = make_float4(sc*v0.x, sc*v0.y, sc*v1.x, sc*v1.y);
                *(float4*)(vp+4) = make_float4(sc*v2.x, sc*v2.y, sc*v3.x, sc*v3.y);
            }
        }
    }
    __syncthreads();

    // ---- phase 3d: write out level 0 from sU
    for (int t=tid; t<1536; t+=NTH)
        vbase[t] = (2.0f/1024.0f) * sU[t];
}

// ------------------------------------------------- segmented 33x33 Gram -> atomic d_G
#define GSTR 260
__global__ void __launch_bounds__(256) k_gram(){
    __shared__ __align__(16) float sm[34*GSTR];
    int seg = blockIdx.x, b = blockIdx.y;
    int tid = threadIdx.x;          // 256
    const float* Vb = d_V + (size_t)b*33*KTOT + seg*SEG;
    for (int r=0; r<33; ++r) sm[r*GSTR+tid] = Vb[(size_t)r*KTOT + tid];
    sm[33*GSTR+tid] = 0.f;
    __syncthreads();
    float* gG = d_G + b*1089;
    if (tid < 153){
        int t = tid;
        int ti = (int)((35.0f - sqrtf(1225.0f - 8.0f*(float)t)) * 0.5f);
        if (ti > 16) ti = 16; if (ti < 0) ti = 0;
        int off = 17*ti - (ti*(ti-1))/2;
        while (off > t){ ti--; off = 17*ti - (ti*(ti-1))/2; }
        while (off + (17-ti) <= t){ off += 17-ti; ti++; }
        int tj = ti + (t - off);
        const float* r0 = sm + (2*ti)*GSTR;
        const float* r1 = r0 + GSTR;
        const float* q0 = sm + (2*tj)*GSTR;
        const float* q1 = q0 + GSTR;
        float a00=0,a01=0,a10=0,a11=0;
        for (int k=0; k<SEG; k+=4){
            float4 x0 = *(const float4*)(r0+k);
            float4 x1 = *(const float4*)(r1+k);
            float4 y0 = *(const float4*)(q0+k);
            float4 y1 = *(const float4*)(q1+k);
            a00 += x0.x*y0.x + x0.y*y0.y + x0.z*y0.z + x0.w*y0.w;
            a01 += x0.x*y1.x + x0.y*y1.y + x0.z*y1.z + x0.w*y1.w;
            a10 += x1.x*y0.x + x1.y*y0.y + x1.z*y0.z + x1.w*y0.w;
            a11 += x1.x*y1.x + x1.y*y1.y + x1.z*y1.z + x1.w*y1.w;
        }
        int i0=2*ti, j0=2*tj;
        int i1=i0+1, j1=j0+1;
        atomicAdd(gG + i0*33+j0, a00);
        if (j1<33) atomicAdd(gG + i0*33+j1, a01);
        if (i1<33) atomicAdd(gG + i1*33+j0, a10);
        if (i1<33 && j1<33) atomicAdd(gG + i1*33+j1, a11);
        if (ti != tj){
            atomicAdd(gG + j0*33+i0, a00);
            if (j1<33) atomicAdd(gG + j1*33+i0, a01);
            if (i1<33) atomicAdd(gG + j0*33+i1, a10);
            if (i1<33 && j1<33) atomicAdd(gG + j1*33+i1, a11);
        }
    }
}

// ------------------------------------------------- stats + Cholesky + logdet
__global__ void k_final(float* __restrict__ out){
    __shared__ float G[1089];
    __shared__ float Mch[32][33];
    __shared__ float sc0;
    int b = blockIdx.x;
    int tid = threadIdx.x;          // 256
    for (int pair=tid; pair<1089; pair+=256) G[pair] = d_G[b*1089 + pair];
    __syncthreads();
    if (tid < 32){
        float dg = G[tid*33+tid];
        for (int o=16;o>0;o>>=1) dg += __shfl_down_sync(0xffffffffu, dg, o);
        if (tid==0){
            float var = dg * (1.0f/32.0f);
            if (var < 1e-6f) var = 1e-6f;
            sc0 = var;
        }
    }
    __syncthreads();
    float var = sc0;
    float inv_var = 1.0f/var;
    for (int t=tid; t<1024; t+=256){
        int i = t>>5, j = t&31;
        Mch[i][j] = G[i*33+j]*inv_var + ((i==j)?EPSR:0.f);
    }
    __syncthreads();
    for (int k=0; k<32; ++k){
        if (tid==0) Mch[k][k] = sqrtf(Mch[k][k]);
        __syncthreads();
        if (tid>k && tid<32) Mch[tid][k] /= Mch[k][k];
        __syncthreads();
        if (tid>k && tid<32){
            float lik = Mch[tid][k];
            for (int j=k+1; j<=tid; ++j) Mch[tid][j] -= lik*Mch[j][k];
        }
        __syncthreads();
    }
    if (tid < 32){
        float ld  = 2.0f*logf(Mch[tid][tid]);
        float zw  = G[tid*33+32];
        float zw2 = zw*zw;
        for (int o=16;o>0;o>>=1){
            ld  += __shfl_down_sync(0xffffffffu, ld,  o);
            zw2 += __shfl_down_sync(0xffffffffu, zw2, o);
        }
        if (tid==0){
            float trace = EPSR*G[32*33+32] + zw2*inv_var;
            out[b] = 0.5f*(ld - trace);
        }
    }
}

// ----------------------------------------------------------------------------
extern "C" void kernel_launch(void* const* d_in, const int* in_sizes, int n_in,
                              void* d_out, int out_size){
    (void)n_in; (void)out_size;
    InPtrs P;
    const float* L; const float* lam;
    if (in_sizes[0] > 1000000){
        // alphabetical: L, lam, w0..w4, z0..z4
        L   = (const float*)d_in[0];
        lam = (const float*)d_in[1];
        for (int l=0;l<5;++l){ P.w[l] = (const float*)d_in[2+l]; P.z[l] = (const float*)d_in[7+l]; }
    } else if (in_sizes[2] == 6144){
        // grouped: z0..z4, w0..w4, L, lam
        for (int l=0;l<5;++l){ P.z[l] = (const float*)d_in[l]; P.w[l] = (const float*)d_in[5+l]; }
        L   = (const float*)d_in[10];
        lam = (const float*)d_in[11];
    } else {
        // dict insertion order: z0,w0,z1,w1,...,L,lam
        for (int l=0;l<5;++l){ P.z[l] = (const float*)d_in[2*l]; P.w[l] = (const float*)d_in[2*l+1]; }
        L   = (const float*)d_in[10];
        lam = (const float*)d_in[11];
    }
    float* out = (float*)d_out;

    static int smem_set = 0;
    if (!smem_set){
        cudaFuncSetAttribute(k_main, cudaFuncAttributeMaxDynamicSharedMemorySize, SMEM_MAIN);
        smem_set = 1;
    }

    k_prep<<<1808, 256>>>(L, lam, P);
    k_main<<<dim3(NM, NB), NTH, SMEM_MAIN>>>();
    k_gram<<<dim3(NSEG, NB), 256>>>();
    k_final<<<NB, 256>>>(out);
}

// round 15
// speedup vs baseline: 1.1610x; 1.1610x over previous
#include <cuda_runtime.h>
#include <cuda_bf16.h>
#include <math.h>

#define NB 4
#define NM 32
#define CT 282
#define CTP 284             // padded row stride for d_At (float4-safe tail)
#define CT2 (CT*CT)
#define KTOT 24576          // 2 * 12288 floats per Gram row
#define SEG 256
#define NSEG 96
#define EPSR 1e-3f
#define NTH 768             // k_main threads
#define NW  24              // warps in k_main

#define SXP2_N 3720         // down-aliased pyramid complex elements per (b,m)
#define SC_N   3720         // C-table complex elements per (b,m)
// sXp2 + sC (float2) + sS (1364 f) + sU (1536 f)
#define SMEM_MAIN ((SXP2_N + SC_N) * 8 + (1364 + 1536) * 4)   // 71120 bytes

// per-level constants
__constant__ int c_h[5]     = {2,4,8,16,32};
__constant__ int c_cnt[5]   = {192,48,24,12,6};
__constant__ int c_cbase[6] = {0,192,240,264,276,282};
__constant__ int c_OffC[5]  = {0,768,1536,3072,6144};   // complex offset of level block in Zh
__constant__ int c_LB2[5]   = {0,0,192,672,1680};       // compact pyramid base per level
__constant__ int c_PS2[5]   = {0,4,20,84,340};          // compact per-channel pyramid size
__constant__ int c_LO[5]    = {0,4,20,84,340};          // offset of level-l slice inside a channel stack

// phase-3 warp-item schedule (46 items over 24 warps, 2 rounds, -1 = idle)
__constant__ int c_perm[48] = {
    0,1,2,3,4,5,6,7,8,9,10,11,12,13,14,15,16,17,18,19,20,21,22,23,
    36,37,38,39,40,41,42,43,44,45,-1,-1,30,31,32,33,34,35,24,25,26,27,28,29
};

// prepA upper-triangular block pairs (9x9 -> 45)
__constant__ int c_pbi[45] = {0,0,0,0,0,0,0,0,0, 1,1,1,1,1,1,1,1, 2,2,2,2,2,2,2,
                              3,3,3,3,3,3, 4,4,4,4,4, 5,5,5,5, 6,6,6, 7,7, 8};
__constant__ int c_pbj[45] = {0,1,2,3,4,5,6,7,8, 1,2,3,4,5,6,7,8, 2,3,4,5,6,7,8,
                              3,4,5,6,7,8, 4,5,6,7,8, 5,6,7,8, 6,7,8, 7,8, 8};

// dft job table: 42 jobs
__constant__ int jb_l[42]  = {0,0,0,0,0,0, 1,1,1,1,1,1, 2,2,2,2,2,2,2,2,2,2,2,2,
                              3,3,3,3,3,3,3,3,3,3,3,3, 4,4,4,4,4,4};
__constant__ int jb_c0[42] = {0,32,64,96,128,160, 0,8,16,24,32,40,
                              0,2,4,6,8,10,12,14,16,18,20,22,
                              0,1,2,3,4,5,6,7,8,9,10,11, 0,1,2,3,4,5};
__constant__ int jb_n[42]  = {32,32,32,32,32,32, 8,8,8,8,8,8, 2,2,2,2,2,2,2,2,2,2,2,2,
                              1,1,1,1,1,1,1,1,1,1,1,1, 1,1,1,1,1,1};

// scratch (device globals; no allocation)
__device__ __align__(16) float d_At[NM*CT*CTP];        // At[m][c][d] (stride CTP)
__device__ float  d_Spyr[NM*1364];                     // alias pyramid of s per mode
__device__ __align__(16) float2 d_Zh[NB*12288];        // per-level DFTs of z
__device__ __align__(16) float  d_V [(size_t)NB*33*KTOT]; // Gram rows (0..31 = U-hat, 32 = w-hat)
__device__ float  d_G [NB*1089];                       // Gram accumulators (atomic)

struct InPtrs { const float* z[5]; const float* w[5]; };

// ----------------------------------------------------------- f32x2 helpers
__device__ __forceinline__ unsigned long long pack2(float a){
    unsigned long long r;
    asm("mov.b64 %0, {%1, %1};" : "=l"(r) : "f"(a));
    return r;
}
__device__ __forceinline__ void ffma2(unsigned long long &d, unsigned long long a, unsigned long long b){
    asm("fma.rn.f32x2 %0, %1, %2, %0;" : "+l"(d) : "l"(a), "l"(b));
}
__device__ __forceinline__ void fadd2(unsigned long long &d, unsigned long long a){
    asm("add.rn.f32x2 %0, %1, %0;" : "+l"(d) : "l"(a));
}
__device__ __forceinline__ void fmul2(unsigned long long &d, unsigned long long a){
    asm("mul.rn.f32x2 %0, %1, %0;" : "+l"(d) : "l"(a));
}
__device__ __forceinline__ float2 unpack2(unsigned long long v){
    float2 r;
    asm("mov.b64 {%0, %1}, %2;" : "=f"(r.x), "=f"(r.y) : "l"(v));
    return r;
}

// 4d x 1k accumulate (ac0..ac3) with broadcast A float4 and one X value
#define ACC4(av, x) do { \
    ffma2(ac0, pack2((av).x), (x)); \
    ffma2(ac1, pack2((av).y), (x)); \
    ffma2(ac2, pack2((av).z), (x)); \
    ffma2(ac3, pack2((av).w), (x)); \
} while(0)

// 4d x 4k accumulate into ac[16] (d-major), X = 4 consecutive complex
#define ACC16A(av, x01, x23) do { \
    unsigned long long A0=pack2((av).x), A1=pack2((av).y); \
    unsigned long long A2=pack2((av).z), A3=pack2((av).w); \
    ffma2(ac[0], A0,(x01).x); ffma2(ac[1], A0,(x01).y); ffma2(ac[2], A0,(x23).x); ffma2(ac[3], A0,(x23).y); \
    ffma2(ac[4], A1,(x01).x); ffma2(ac[5], A1,(x01).y); ffma2(ac[6], A1,(x23).x); ffma2(ac[7], A1,(x23).y); \
    ffma2(ac[8], A2,(x01).x); ffma2(ac[9], A2,(x01).y); ffma2(ac[10],A2,(x23).x); ffma2(ac[11],A2,(x23).y); \
    ffma2(ac[12],A3,(x01).x); ffma2(ac[13],A3,(x01).y); ffma2(ac[14],A3,(x23).x); ffma2(ac[15],A3,(x23).y); \
} while(0)

// ============= fused preprocessing: prepA (blocks 0..1439), spyr (1440..1471), dft (1472..1807)
__global__ void __launch_bounds__(256) k_prep(const float* __restrict__ L,
                                              const float* __restrict__ lam,
                                              InPtrs P){
    __shared__ float sh[3136];
    int bx = blockIdx.x;
    int tid = threadIdx.x;

    if (bx < 1440){
        // ---------------- At = L^T - L, pair-tiled (32x32 pair per block)
        float (*Ta)[33] = (float(*)[33])sh;
        float (*Tb)[33] = (float(*)[33])(sh + 1056);
        int m = bx / 45, p = bx - m*45;
        int i0 = c_pbi[p]*32, j0 = c_pbj[p]*32;
        int tx = tid & 31, ty0 = tid >> 5;
        const float* Lm = L + (size_t)m*CT2;
        #pragma unroll
        for (int rr=0; rr<4; ++rr){
            int ty = ty0 + rr*8;
            int r = i0+ty, c = j0+tx;
            Ta[ty][tx] = (r<CT && c<CT) ? Lm[r*CT + c] : 0.f;
            r = j0+ty; c = i0+tx;
            Tb[ty][tx] = (r<CT && c<CT) ? Lm[r*CT + c] : 0.f;
        }
        __syncthreads();
        #pragma unroll
        for (int rr=0; rr<4; ++rr){
            int ty = ty0 + rr*8;
            if (i0+ty<CT && j0+tx<CT)
                d_At[((size_t)m*CT + i0+ty)*CTP + j0+tx] = Ta[ty][tx] - Tb[tx][ty];
            if (j0+ty<CT && i0+tx<CT)
                d_At[((size_t)m*CT + j0+ty)*CTP + i0+tx] = Tb[ty][tx] - Ta[tx][ty];
        }
    } else if (bx < 1472){
        // ---------------- s pyramid + zero d_G
        float* sA = sh;           // 1024
        float* sB = sh + 1024;    // 256
        int m = bx - 1440;
        int gidx = m*256 + tid;
        if (gidx < NB*1089) d_G[gidx] = 0.f;
        const float* lm = lam + m*1024;
        for (int t=tid; t<1024; t+=256){
            int p = t>>5, q = t&31;
            float v = lm[t] - lm[(((32-p)&31)<<5) + ((32-q)&31)];
            sA[t] = v;
            d_Spyr[m*1364 + 340 + t] = v;
        }
        float* src = sA; float* dst = sB;
        int hs = 32;
        for (int k=0; k<4; ++k){
            __syncthreads();
            int hn = hs>>1;
            int off = c_LO[3-k];        // 84,20,4,0
            for (int t=tid; t<hn*hn; t+=256){
                int p = t/hn, q = t-p*hn;
                float v = src[p*hs+q] + src[(p+hn)*hs+q]
                        + src[p*hs+q+hn] + src[(p+hn)*hs+q+hn];
                dst[t] = v;
                d_Spyr[m*1364 + off + t] = v;
            }
            float* tmp = src; src = dst; dst = tmp;
            hs = hn;
        }
    } else {
        // ---------------- batched small 2D DFTs of z (and w -> V row 32)
        float* sIn = sh;            // 1024
        float* tRe = sh + 1024;     // 1024
        float* tIm = sh + 2048;     // 1024
        float2* tw = (float2*)(sh + 3072);  // 32
        int idx = bx - 1472;
        int j = idx % 42;
        int t2 = idx / 42;
        int b = t2 & 3, isw = t2 >> 2;
        int l = jb_l[j];
        int h = c_h[l], hm = h-1;
        int lh = 31 - __clz(h);
        int lh2 = 2*lh;
        int h2 = h*h;
        int c0 = jb_c0[j], nch = jb_n[j];
        int npts = nch*h2;
        const float* in = (isw ? P.w[l] : P.z[l]) + (size_t)(b*c_cnt[l] + c0)*h2;
        if (tid < h){
            float sn, cn; __sincosf(-6.283185307179586f*(float)tid/(float)h, &sn, &cn);
            tw[tid] = make_float2(cn, sn);
        }
        for (int t=tid; t<npts; t+=256) sIn[t] = in[t];
        __syncthreads();
        for (int t=tid; t<npts; t+=256){
            int ch = t>>lh2;
            int pt = t & (h2-1);
            int p = pt>>lh, x = pt&hm;
            const float* base = sIn + (ch<<lh2) + x;
            float ar=0.f, ai=0.f;
            for (int y=0; y<h; ++y){
                float2 e = tw[(p*y)&hm];
                float v = base[y<<lh];
                ar += v*e.x; ai += v*e.y;
            }
            tRe[t]=ar; tIm[t]=ai;
        }
        __syncthreads();
        float inv = 1.0f/(float)h;
        float* vrow = d_V + ((size_t)(b*33+32))*KTOT;
        for (int t=tid; t<npts; t+=256){
            int ch = t>>lh2;
            int pt = t & (h2-1);
            int p = pt>>lh, q = pt&hm;
            const float* bR = tRe + (ch<<lh2) + (p<<lh);
            const float* bI = tIm + (ch<<lh2) + (p<<lh);
            float ar=0.f, ai=0.f;
            for (int x=0; x<h; ++x){
                float2 e = tw[(q*x)&hm];
                float re = bR[x], im = bI[x];
                ar += re*e.x - im*e.y;
                ai += re*e.y + im*e.x;
            }
            int kk = c_OffC[l] + (c0<<lh2) + t;
            if (!isw){
                d_Zh[b*12288 + kk] = make_float2(ar, ai);
            } else {
                vrow[2*kk  ] =  ai*inv;
                vrow[2*kk+1] = -ar*inv;
            }
        }
    }
}

// 4-point downward alias within compact pyramid (smem)
__device__ __forceinline__ void alias_down(float2* __restrict__ sXp2,
                                           int lc, int lt, int ch, int pt){
    int ht = c_h[lt], hsrc = ht*2;
    int p = pt / ht, q = pt - p*ht;
    float2* base = sXp2 + c_LB2[lc] + ch*c_PS2[lc];
    const float2* src = base + c_LO[lt+1];
    float2 a0=src[p*hsrc+q],        a1=src[(p+ht)*hsrc+q];
    float2 a2=src[p*hsrc+q+ht],     a3=src[(p+ht)*hsrc+q+ht];
    base[c_LO[lt]+pt] = make_float2(a0.x+a1.x+a2.x+a3.x, a0.y+a1.y+a2.y+a3.y);
}

// ====================== fused per-(b,m) vector-field kernel ======================
__global__ void __launch_bounds__(NTH) k_main(){
    extern __shared__ float smraw[];
    float2* sXp2 = (float2*)smraw;             // [SXP2_N]
    float2* sC   = sXp2 + SXP2_N;              // [SC_N]
    float*  sS   = (float*)(sC + SC_N);        // [1364]
    float*  sU   = sS + 1364;                  // [1536] level-0 accumulators
    int m = blockIdx.x, b = blockIdx.y;
    int tid = threadIdx.x;
    int wid = tid >> 5, lane = tid & 31;

    for (int t=tid; t<1364; t+=NTH) sS[t] = d_Spyr[m*1364 + t];
    for (int t=tid; t<1536; t+=NTH) sU[t] = 0.f;
    for (int t=tid; t<720;  t+=NTH) ((float*)sC)[t] = 0.f;   // ls=0 C region (atomic)
    __syncthreads();

    const float2* Zb = d_Zh + b*12288;
    const float*  Atm = d_At + (size_t)m*CT*CTP;

    // ---- phase 1A: top stored slice per channel (4-pt alias from global Z x S)
    for (int t=tid; t<2880; t+=NTH){
        int lc, ch, pt;
        if (t<192){lc=1; ch=t>>2; pt=t&3;}
        else if (t<576){lc=2; int u=t-192; ch=u>>4; pt=u&15;}
        else if (t<1344){lc=3; int u=t-576; ch=u>>6; pt=u&63;}
        else {lc=4; int u=t-1344; ch=u>>8; pt=u&255;}
        int ht = c_h[lc-1], hs = ht*2;
        int p = pt / ht, q = pt - p*ht;
        const float* Sl = sS + c_LO[lc];
        const float2* Zc = Zb + c_OffC[lc] + ch*hs*hs;
        float ar=0.f, ai=0.f;
        #pragma unroll
        for (int i=0;i<2;++i){
            #pragma unroll
            for (int jj=0;jj<2;++jj){
                int idx = (p+i*ht)*hs + (q+jj*ht);
                float s = Sl[idx];
                float2 z = Zc[idx];
                ar += s*z.x; ai += s*z.y;
            }
        }
        sXp2[c_LB2[lc] + ch*c_PS2[lc] + c_LO[lc-1] + pt] = make_float2(ar, ai);
    }
    __syncthreads();

    // ---- phase 1B: downward aliasing within smem (3 rounds)
    for (int t=tid; t<672; t+=NTH){
        if (t<96)       alias_down(sXp2, 2, 0, t>>2, t&3);
        else if (t<288){int u=t-96;  alias_down(sXp2, 3, 1, u>>4, u&15);}
        else           {int u=t-288; alias_down(sXp2, 4, 2, u>>6, u&63);}
    }
    __syncthreads();
    for (int t=tid; t<144; t+=NTH){
        if (t<48)      alias_down(sXp2, 3, 0, t>>2, t&3);
        else          {int u=t-48; alias_down(sXp2, 4, 1, u>>4, u&15);}
    }
    __syncthreads();
    for (int t=tid; t<24; t+=NTH) alias_down(sXp2, 4, 0, t>>2, t&3);
    __syncthreads();

    // ---- phase 2: C table, warp-cooperative (63 warp-items)
    for (int it = wid; it < 63; it += NW){
        if (it < 12){
            // ls0: lane = d (32 per group, 3 groups: 0..95, valid <90), 4 residues in regs
            int g = it >> 2, cc = it & 3;
            int di = g*32 + lane;
            bool ok = di < 90;
            int diL = ok ? di : 89;
            int clo = cc*48, chi = clo+48;
            unsigned long long a0=0ull,a1=0ull,a2=0ull,a3=0ull;
            const float* ap = Atm + (size_t)clo*CTP + 192 + diL;
            const ulonglong2* zp = (const ulonglong2*)((const unsigned long long*)Zb + clo*4);
            for (int c=clo; c<chi; ++c){
                unsigned long long av = pack2(__ldg(ap));
                ulonglong2 z01 = zp[0];
                ulonglong2 z23 = zp[1];
                ffma2(a0,av,z01.x); ffma2(a1,av,z01.y);
                ffma2(a2,av,z23.x); ffma2(a3,av,z23.y);
                ap += CTP; zp += 2;
            }
            if (ok){
                float* f = (float*)sC + di*8;
                float2 v;
                v=unpack2(a0); atomicAdd(f+0,v.x); atomicAdd(f+1,v.y);
                v=unpack2(a1); atomicAdd(f+2,v.x); atomicAdd(f+3,v.y);
                v=unpack2(a2); atomicAdd(f+4,v.x); atomicAdd(f+5,v.y);
                v=unpack2(a3); atomicAdd(f+6,v.x); atomicAdd(f+7,v.y);
            }
        } else if (it < 33){                 // ls1: 21 items, 2 di x 16 r
            int ii = it - 12;
            int di = ii*2 + (lane>>4);       // 0..41
            int r  = lane & 15;
            unsigned long long acc = 0ull;
            const float* ap = Atm + (size_t)192*CTP + 240 + di;
            const unsigned long long* zp = (const unsigned long long*)(Zb + 768) + r;
            for (int c=0;c<48;++c){
                ffma2(acc, pack2(__ldg(ap)), zp[(size_t)c*16]);
                ap += CTP;
            }
            ((unsigned long long*)sC)[360 + di*16 + r] = acc;
        } else if (it < 51){                 // ls2: 18 items, 1 di x 64 r (2/lane)
            int di = it - 33;
            int r0 = lane*2;
            unsigned long long a0=0ull, a1=0ull;
            const float* ap = Atm + (size_t)240*CTP + 264 + di;
            const ulonglong2* zp = (const ulonglong2*)(Zb + 1536 + r0);
            for (int c=0;c<24;++c){
                unsigned long long av = pack2(__ldg(ap));
                ulonglong2 z = zp[(size_t)c*32];
                ffma2(a0, av, z.x); ffma2(a1, av, z.y);
                ap += CTP;
            }
            unsigned long long* Cu = (unsigned long long*)sC + 1032 + di*64 + r0;
            Cu[0]=a0; Cu[1]=a1;
        } else {                             // ls3: 12 items, (di, kt), 4 r/lane
            int u = it - 51;
            int di = u >> 1, kt = u & 1;
            int r0 = kt*128 + lane*4;
            unsigned long long a0=0ull,a1=0ull,a2=0ull,a3=0ull;
            const float* ap = Atm + (size_t)264*CTP + 276 + di;
            const ulonglong2* zp = (const ulonglong2*)(Zb + 3072 + r0);
            for (int c=0;c<12;++c){
                unsigned long long av = pack2(__ldg(ap));
                ulonglong2 z01 = zp[(size_t)c*128];
                ulonglong2 z23 = zp[(size_t)c*128 + 1];
                ffma2(a0,av,z01.x); ffma2(a1,av,z01.y);
                ffma2(a2,av,z23.x); ffma2(a3,av,z23.y);
                ap += CTP;
            }
            unsigned long long* Cu = (unsigned long long*)sC + 2184 + di*256 + r0;
            Cu[0]=a0; Cu[1]=a1; Cu[2]=a2; Cu[3]=a3;
        }
    }
    __syncthreads();

    // ---- phase 3: mixing, warp-cooperative (46 warp-items, 2-round snake schedule)
    float* vbase = d_V + ((size_t)(b*33+m))*KTOT;
    const unsigned long long* Cb0 = (const unsigned long long*)sC;
    for (int s = wid; s < 48; s += NW){
        int it = c_perm[s];
        if (it < 0) continue;

        if (it < 12){
            // l0: lane = d (32 per group, 6 groups), 4 k in regs; 2 channel-chunks
            int g = it >> 1, chunk = it & 1;
            int d = g*32 + lane;
            unsigned long long ac0=0ull,ac1=0ull,ac2=0ull,ac3=0ull;
            int clo = chunk ? 141 : 0;
            int ce  = chunk ? 192 : 141;
            {
                const float* ap = Atm + (size_t)clo*CTP + d;
                const ulonglong2* zp = (const ulonglong2*)((const unsigned long long*)Zb + clo*4);
                for (int c=clo; c<ce; ++c){
                    unsigned long long av = pack2(__ldg(ap));
                    ulonglong2 x01 = zp[0];
                    ulonglong2 x23 = zp[1];
                    ffma2(ac0,av,x01.x); ffma2(ac1,av,x01.y);
                    ffma2(ac2,av,x23.x); ffma2(ac3,av,x23.y);
                    ap += CTP; zp += 2;
                }
                fmul2(ac0, pack2(sS[0])); fmul2(ac1, pack2(sS[1]));
                fmul2(ac2, pack2(sS[2])); fmul2(ac3, pack2(sS[3]));
            }
            if (chunk){
                for (int lc=1; lc<5; ++lc){
                    int cb=c_cbase[lc], ce2=c_cbase[lc+1];
                    int ps2 = c_PS2[lc] >> 1;    // stride in ulonglong2 units
                    const ulonglong2* xp = (const ulonglong2*)(sXp2 + c_LB2[lc]);
                    const float* ap = Atm + (size_t)cb*CTP + d;
                    for (int c=cb;c<ce2;++c){
                        unsigned long long av = pack2(__ldg(ap));
                        ulonglong2 x01 = xp[0];
                        ulonglong2 x23 = xp[1];
                        ffma2(ac0,av,x01.x); ffma2(ac1,av,x01.y);
                        ffma2(ac2,av,x23.x); ffma2(ac3,av,x23.y);
                        ap += CTP; xp += ps2;
                    }
                }
            }
            float* u = sU + d*8;
            float2 v;
            v=unpack2(ac0); atomicAdd(u+0,v.x); atomicAdd(u+1,v.y);
            v=unpack2(ac1); atomicAdd(u+2,v.x); atomicAdd(u+3,v.y);
            v=unpack2(ac2); atomicAdd(u+4,v.x); atomicAdd(u+5,v.y);
            v=unpack2(ac3); atomicAdd(u+6,v.x); atomicAdd(u+7,v.y);
        } else if (it < 18){
            // l1: 8 d x 16 k; lanes = (dl in 2, k in 16)
            int ii = it - 12;
            int dl = lane >> 4;
            int k  = lane & 15;
            int d0 = 192 + ii*8 + dl*4;
            int p = k>>2, q = k&3;
            int r = (p&1)*2 + (q&1);
            unsigned long long ac0 = Cb0[(d0-192)*4 + r];
            unsigned long long ac1 = Cb0[(d0-191)*4 + r];
            unsigned long long ac2 = Cb0[(d0-190)*4 + r];
            unsigned long long ac3 = Cb0[(d0-189)*4 + r];
            {
                const float* ap = Atm + (size_t)192*CTP + d0;
                const unsigned long long* zp = (const unsigned long long*)(Zb + 768) + k;
                for (int c=0;c<48;++c){
                    float4 av = __ldg((const float4*)ap);
                    unsigned long long x = zp[(size_t)c*16];
                    ACC4(av, x);
                    ap += CTP;
                }
                unsigned long long s2 = pack2(sS[4+k]);
                fmul2(ac0,s2); fmul2(ac1,s2); fmul2(ac2,s2); fmul2(ac3,s2);
            }
            for (int lc=2; lc<5; ++lc){
                int cb=c_cbase[lc], ce2=c_cbase[lc+1];
                int ps=c_PS2[lc];
                const unsigned long long* xp = (const unsigned long long*)(sXp2 + c_LB2[lc]) + 4 + k;
                const float* ap = Atm + (size_t)cb*CTP + d0;
                for (int c=cb;c<ce2;++c){
                    float4 av = __ldg((const float4*)ap);
                    unsigned long long x = *xp;
                    ACC4(av, x);
                    ap += CTP; xp += ps;
                }
            }
            const float sc = 4.0f/1024.0f;
            float* vp = vbase + 2*(768 + (d0-192)*16 + k);
            float2 v;
            v=unpack2(ac0); vp[0]=sc*v.x;  vp[1]=sc*v.y;
            v=unpack2(ac1); vp[32]=sc*v.x; vp[33]=sc*v.y;
            v=unpack2(ac2); vp[64]=sc*v.x; vp[65]=sc*v.y;
            v=unpack2(ac3); vp[96]=sc*v.x; vp[97]=sc*v.y;
        } else if (it < 24){
            // l2: 4 d x 64 k; lanes = 2 k each
            int dg = it - 18;
            int d0 = 240 + dg*4;
            int k0 = lane*2;
            unsigned long long ac[8];
            #pragma unroll
            for (int j=0;j<2;++j){
                int k = k0+j;
                int p=k>>3, q=k&7;
                int r0=(p&1)*2+(q&1), r1=(p&3)*4+(q&3);
                #pragma unroll
                for (int dj=0;dj<4;++dj){
                    unsigned long long a = Cb0[(d0-192+dj)*4 + r0];
                    fadd2(a, Cb0[360 + (d0-240+dj)*16 + r1]);
                    ac[dj*2+j] = a;
                }
            }
            {
                const float* ap = Atm + (size_t)240*CTP + d0;
                const ulonglong2* zp = (const ulonglong2*)(Zb + 1536 + k0);
                for (int c=0;c<24;++c){
                    float4 av = __ldg((const float4*)ap);
                    ulonglong2 x = zp[(size_t)c*32];
                    unsigned long long A0=pack2(av.x),A1=pack2(av.y),A2=pack2(av.z),A3=pack2(av.w);
                    ffma2(ac[0],A0,x.x); ffma2(ac[1],A0,x.y);
                    ffma2(ac[2],A1,x.x); ffma2(ac[3],A1,x.y);
                    ffma2(ac[4],A2,x.x); ffma2(ac[5],A2,x.y);
                    ffma2(ac[6],A3,x.x); ffma2(ac[7],A3,x.y);
                    ap += CTP;
                }
                unsigned long long s0 = pack2(sS[20+k0]);
                unsigned long long s1 = pack2(sS[21+k0]);
                fmul2(ac[0],s0); fmul2(ac[1],s1);
                fmul2(ac[2],s0); fmul2(ac[3],s1);
                fmul2(ac[4],s0); fmul2(ac[5],s1);
                fmul2(ac[6],s0); fmul2(ac[7],s1);
            }
            for (int lc=3; lc<5; ++lc){
                int cb=c_cbase[lc], ce2=c_cbase[lc+1];
                int ps2 = c_PS2[lc]>>1;
                const ulonglong2* xp = (const ulonglong2*)(sXp2 + c_LB2[lc] + 20 + k0);
                const float* ap = Atm + (size_t)cb*CTP + d0;
                for (int c=cb;c<ce2;++c){
                    float4 av = __ldg((const float4*)ap);
                    ulonglong2 x = *xp;
                    unsigned long long A0=pack2(av.x),A1=pack2(av.y),A2=pack2(av.z),A3=pack2(av.w);
                    ffma2(ac[0],A0,x.x); ffma2(ac[1],A0,x.y);
                    ffma2(ac[2],A1,x.x); ffma2(ac[3],A1,x.y);
                    ffma2(ac[4],A2,x.x); ffma2(ac[5],A2,x.y);
                    ffma2(ac[6],A3,x.x); ffma2(ac[7],A3,x.y);
                    ap += CTP; xp += ps2;
                }
            }
            const float sc = 8.0f/1024.0f;
            #pragma unroll
            for (int dj=0;dj<4;++dj){
                float* vp = vbase + 2*(1536 + (d0-240+dj)*64 + k0);
                float2 va=unpack2(ac[dj*2]), vb=unpack2(ac[dj*2+1]);
                *(float4*)vp = make_float4(sc*va.x, sc*va.y, sc*vb.x, sc*vb.y);
            }
        } else if (it < 30){
            // l3: 4 d x 128 k; lanes = 4 k each
            int u = it - 24;
            int dg = u >> 1, kt = u & 1;
            int d0 = 264 + dg*4;
            int k0 = kt*128 + lane*4;
            unsigned long long ac[16];
            int p = k0 >> 4, q0 = k0 & 15;
            #pragma unroll
            for (int j=0;j<4;++j){
                int q = q0 + j;
                int r0=(p&1)*2+(q&1), r1=(p&3)*4+(q&3), r2=(p&7)*8+(q&7);
                #pragma unroll
                for (int dj=0;dj<4;++dj){
                    unsigned long long a = Cb0[(d0-192+dj)*4 + r0];
                    fadd2(a, Cb0[360 + (d0-240+dj)*16 + r1]);
                    fadd2(a, Cb0[1032 + (d0-264+dj)*64 + r2]);
                    ac[dj*4+j] = a;
                }
            }
            {
                const float* ap = Atm + (size_t)264*CTP + d0;
                const ulonglong2* zp = (const ulonglong2*)(Zb + 3072 + k0);
                for (int c=0;c<12;++c){
                    float4 av = __ldg((const float4*)ap);
                    ulonglong2 x01 = zp[(size_t)c*128];
                    ulonglong2 x23 = zp[(size_t)c*128 + 1];
                    ACC16A(av, x01, x23);
                    ap += CTP;
                }
                #pragma unroll
                for (int j=0;j<4;++j){
                    unsigned long long s2 = pack2(sS[84 + k0 + j]);
                    fmul2(ac[j],s2); fmul2(ac[4+j],s2); fmul2(ac[8+j],s2); fmul2(ac[12+j],s2);
                }
            }
            {
                const ulonglong2* xp = (const ulonglong2*)(sXp2 + 1680 + 84 + k0);
                const float* ap = Atm + (size_t)276*CTP + d0;
                for (int c=0;c<6;++c){
                    float4 av = __ldg((const float4*)ap);
                    ulonglong2 x01 = xp[0];
                    ulonglong2 x23 = xp[1];
                    ACC16A(av, x01, x23);
                    ap += CTP; xp += 170;
                }
            }
            const float sc = 16.0f/1024.0f;
            #pragma unroll
            for (int dj=0;dj<4;++dj){
                float* vp = vbase + 2*(3072 + (d0-264+dj)*256 + k0);
                float2 v0=unpack2(ac[dj*4+0]), v1=unpack2(ac[dj*4+1]);
                float2 v2=unpack2(ac[dj*4+2]), v3=unpack2(ac[dj*4+3]);
                *(float4*)vp     = make_float4(sc*v0.x, sc*v0.y, sc*v1.x, sc*v1.y);
                *(float4*)(vp+4) = make_float4(sc*v2.x, sc*v2.y, sc*v3.x, sc*v3.y);
            }
        } else {
            // l4: up to 4 d x 128 k; lanes = 4 k each
            int u = it - 30;
            int dg = u >> 3, kt = u & 7;
            int d0 = 276 + dg*4;
            int dcnt = 282 - d0; if (dcnt>4) dcnt=4;
            int k0 = kt*128 + lane*4;
            unsigned long long ac[16];
            int p = k0 >> 5, q0 = k0 & 31;
            #pragma unroll
            for (int j=0;j<4;++j){
                int q = q0 + j;
                int r0=(p&1)*2+(q&1), r1=(p&3)*4+(q&3);
                int r2=(p&7)*8+(q&7), r3=(p&15)*16+(q&15);
                #pragma unroll
                for (int dj=0;dj<4;++dj){
                    unsigned long long a = Cb0[(d0-192+dj)*4 + r0];
                    fadd2(a, Cb0[360 + (d0-240+dj)*16 + r1]);
                    fadd2(a, Cb0[1032 + (d0-264+dj)*64 + r2]);
                    fadd2(a, Cb0[2184 + (d0-276+dj)*256 + r3]);
                    ac[dj*4+j] = a;
                }
            }
            {
                const float* ap = Atm + (size_t)276*CTP + d0;
                const ulonglong2* zp = (const ulonglong2*)(Zb + 6144 + k0);
                for (int c=0;c<6;++c){
                    float4 av = __ldg((const float4*)ap);
                    ulonglong2 x01 = zp[(size_t)c*512];
                    ulonglong2 x23 = zp[(size_t)c*512 + 1];
                    ACC16A(av, x01, x23);
                    ap += CTP;
                }
                #pragma unroll
                for (int j=0;j<4;++j){
                    unsigned long long s2 = pack2(sS[340 + k0 + j]);
                    fmul2(ac[j],s2); fmul2(ac[4+j],s2); fmul2(ac[8+j],s2); fmul2(ac[12+j],s2);
                }
            }
            const float sc = 32.0f/1024.0f;
            for (int dj=0;dj<dcnt;++dj){
                float* vp = vbase + 2*(6144 + (d0-276+dj)*1024 + k0);
                float2 v0=unpack2(ac[dj*4+0]), v1=unpack2(ac[dj*4+1]);
                float2 v2=unpack2(ac[dj*4+2]), v3=unpack2(ac[dj*4+3]);
                *(float4*)vp     = make_float4(sc*v0.x, sc*v0.y, sc*v1.x, sc*v1.y);
                *(float4*)(vp+4) = make_float4(sc*v2.x, sc*v2.y, sc*v3.x, sc*v3.y);
            }
        }
    }
    __syncthreads();

    // ---- phase 3d: write out level 0 from sU
    for (int t=tid; t<1536; t+=NTH)
        vbase[t] = (2.0f/1024.0f) * sU[t];
}

// ------------------------------------------------- segmented 33x33 Gram -> atomic d_G
#define GSTR 260
__global__ void __launch_bounds__(256) k_gram(){
    __shared__ __align__(16) float sm[34*GSTR];
    int seg = blockIdx.x, b = blockIdx.y;
    int tid = threadIdx.x;          // 256
    const float* Vb = d_V + (size_t)b*33*KTOT + seg*SEG;
    for (int r=0; r<33; ++r) sm[r*GSTR+tid] = Vb[(size_t)r*KTOT + tid];
    sm[33*GSTR+tid] = 0.f;
    __syncthreads();
    float* gG = d_G + b*1089;
    if (tid < 153){
        int t = tid;
        int ti = (int)((35.0f - sqrtf(1225.0f - 8.0f*(float)t)) * 0.5f);
        if (ti > 16) ti = 16; if (ti < 0) ti = 0;
        int off = 17*ti - (ti*(ti-1))/2;
        while (off > t){ ti--; off = 17*ti - (ti*(ti-1))/2; }
        while (off + (17-ti) <= t){ off += 17-ti; ti++; }
        int tj = ti + (t - off);
        const float* r0 = sm + (2*ti)*GSTR;
        const float* r1 = r0 + GSTR;
        const float* q0 = sm + (2*tj)*GSTR;
        const float* q1 = q0 + GSTR;
        float a00=0,a01=0,a10=0,a11=0;
        for (int k=0; k<SEG; k+=4){
            float4 x0 = *(const float4*)(r0+k);
            float4 x1 = *(const float4*)(r1+k);
            float4 y0 = *(const float4*)(q0+k);
            float4 y1 = *(const float4*)(q1+k);
            a00 += x0.x*y0.x + x0.y*y0.y + x0.z*y0.z + x0.w*y0.w;
            a01 += x0.x*y1.x + x0.y*y1.y + x0.z*y1.z + x0.w*y1.w;
            a10 += x1.x*y0.x + x1.y*y0.y + x1.z*y0.z + x1.w*y0.w;
            a11 += x1.x*y1.x + x1.y*y1.y + x1.z*y1.z + x1.w*y1.w;
        }
        int i0=2*ti, j0=2*tj;
        int i1=i0+1, j1=j0+1;
        atomicAdd(gG + i0*33+j0, a00);
        if (j1<33) atomicAdd(gG + i0*33+j1, a01);
        if (i1<33) atomicAdd(gG + i1*33+j0, a10);
        if (i1<33 && j1<33) atomicAdd(gG + i1*33+j1, a11);
        if (ti != tj){
            atomicAdd(gG + j0*33+i0, a00);
            if (j1<33) atomicAdd(gG + j1*33+i0, a01);
            if (i1<33) atomicAdd(gG + j0*33+i1, a10);
            if (i1<33 && j1<33) atomicAdd(gG + j1*33+i1, a11);
        }
    }
}

// ------------------------------------------------- stats + parallel Cholesky + logdet
__global__ void k_final(float* __restrict__ out){
    __shared__ float G[1089];
    __shared__ float Mch[32][33];
    __shared__ float sc0, sInv;
    int b = blockIdx.x;
    int tid = threadIdx.x;          // 256
    for (int pair=tid; pair<1089; pair+=256) G[pair] = d_G[b*1089 + pair];
    __syncthreads();
    if (tid < 32){
        float dg = G[tid*33+tid];
        for (int o=16;o>0;o>>=1) dg += __shfl_down_sync(0xffffffffu, dg, o);
        if (tid==0){
            float var = dg * (1.0f/32.0f);
            if (var < 1e-6f) var = 1e-6f;
            sc0 = var;
        }
    }
    __syncthreads();
    float var = sc0;
    float inv_var = 1.0f/var;
    for (int t=tid; t<1024; t+=256){
        int i = t>>5, j = t&31;
        Mch[i][j] = G[i*33+j]*inv_var + ((i==j)?EPSR:0.f);
    }
    __syncthreads();
    // parallel right-looking Cholesky (lower triangle)
    int ui = tid >> 5, uj = tid & 31;   // each thread owns rows ui, ui+8, ui+16, ui+24 at col uj
    for (int k=0; k<32; ++k){
        if (tid==0){
            float s = sqrtf(Mch[k][k]);
            Mch[k][k] = s;
            sInv = 1.0f/s;
        }
        __syncthreads();
        if (tid>k && tid<32) Mch[tid][k] *= sInv;
        __syncthreads();
        #pragma unroll
        for (int rr=0; rr<4; ++rr){
            int i = ui + rr*8;
            if (i>k && uj>k && uj<=i)
                Mch[i][uj] -= Mch[i][k]*Mch[uj][k];
        }
        __syncthreads();
    }
    if (tid < 32){
        float ld  = 2.0f*logf(Mch[tid][tid]);
        float zw  = G[tid*33+32];
        float zw2 = zw*zw;
        for (int o=16;o>0;o>>=1){
            ld  += __shfl_down_sync(0xffffffffu, ld,  o);
            zw2 += __shfl_down_sync(0xffffffffu, zw2, o);
        }
        if (tid==0){
            float trace = EPSR*G[32*33+32] + zw2*inv_var;
            out[b] = 0.5f*(ld - trace);
        }
    }
}

// ----------------------------------------------------------------------------
extern "C" void kernel_launch(void* const* d_in, const int* in_sizes, int n_in,
                              void* d_out, int out_size){
    (void)n_in; (void)out_size;
    InPtrs P;
    const float* L; const float* lam;
    if (in_sizes[0] > 1000000){
        // alphabetical: L, lam, w0..w4, z0..z4
        L   = (const float*)d_in[0];
        lam = (const float*)d_in[1];
        for (int l=0;l<5;++l){ P.w[l] = (const float*)d_in[2+l]; P.z[l] = (const float*)d_in[7+l]; }
    } else if (in_sizes[2] == 6144){
        // grouped: z0..z4, w0..w4, L, lam
        for (int l=0;l<5;++l){ P.z[l] = (const float*)d_in[l]; P.w[l] = (const float*)d_in[5+l]; }
        L   = (const float*)d_in[10];
        lam = (const float*)d_in[11];
    } else {
        // dict insertion order: z0,w0,z1,w1,...,L,lam
        for (int l=0;l<5;++l){ P.z[l] = (const float*)d_in[2*l]; P.w[l] = (const float*)d_in[2*l+1]; }
        L   = (const float*)d_in[10];
        lam = (const float*)d_in[11];
    }
    float* out = (float*)d_out;

    static int smem_set = 0;
    if (!smem_set){
        cudaFuncSetAttribute(k_main, cudaFuncAttributeMaxDynamicSharedMemorySize, SMEM_MAIN);
        smem_set = 1;
    }

    k_prep<<<1808, 256>>>(L, lam, P);
    k_main<<<dim3(NM, NB), NTH, SMEM_MAIN>>>();
    k_gram<<<dim3(NSEG, NB), 256>>>();
    k_final<<<NB, 256>>>(out);
}

// round 16
// speedup vs baseline: 1.2429x; 1.0706x over previous
#include <cuda_runtime.h>
#include <cuda_bf16.h>
#include <math.h>

#define NB 4
#define NM 32
#define CT 282
#define CTP 284             // padded row stride for d_At (float4-safe tail)
#define CT2 (CT*CT)
#define KTOT 24576          // 2 * 12288 floats per Gram row
#define SEG 256
#define NSEG 96
#define EPSR 1e-3f
#define NTH 768             // k_main threads
#define NW  24              // warps in k_main

#define SXP2_N 3720         // down-aliased pyramid complex elements per (b,m)
#define SC_N   3720         // C-table complex elements per (b,m)
// sXp2 + sC (float2) + sS (1364 f) + sU (1536 f)
#define SMEM_MAIN ((SXP2_N + SC_N) * 8 + (1364 + 1536) * 4)   // 71120 bytes

// per-level constants
__constant__ int c_h[5]     = {2,4,8,16,32};
__constant__ int c_cnt[5]   = {192,48,24,12,6};
__constant__ int c_cbase[6] = {0,192,240,264,276,282};
__constant__ int c_OffC[5]  = {0,768,1536,3072,6144};   // complex offset of level block in Zh
__constant__ int c_LB2[5]   = {0,0,192,672,1680};       // compact pyramid base per level
__constant__ int c_PS2[5]   = {0,4,20,84,340};          // compact per-channel pyramid size
__constant__ int c_LO[5]    = {0,4,20,84,340};          // offset of level-l slice inside a channel stack

// phase-3 warp-item schedule (46 items over 24 warps, 2 rounds, -1 = idle)
__constant__ int c_perm[48] = {
    0,1,2,3,4,5,6,7,8,9,10,11,12,13,14,15,16,17,18,19,20,21,22,23,
    36,37,38,39,40,41,42,43,44,45,-1,-1,30,31,32,33,34,35,24,25,26,27,28,29
};

// prepA upper-triangular block pairs (9x9 -> 45)
__constant__ int c_pbi[45] = {0,0,0,0,0,0,0,0,0, 1,1,1,1,1,1,1,1, 2,2,2,2,2,2,2,
                              3,3,3,3,3,3, 4,4,4,4,4, 5,5,5,5, 6,6,6, 7,7, 8};
__constant__ int c_pbj[45] = {0,1,2,3,4,5,6,7,8, 1,2,3,4,5,6,7,8, 2,3,4,5,6,7,8,
                              3,4,5,6,7,8, 4,5,6,7,8, 5,6,7,8, 6,7,8, 7,8, 8};

// dft job table: 42 jobs
__constant__ int jb_l[42]  = {0,0,0,0,0,0, 1,1,1,1,1,1, 2,2,2,2,2,2,2,2,2,2,2,2,
                              3,3,3,3,3,3,3,3,3,3,3,3, 4,4,4,4,4,4};
__constant__ int jb_c0[42] = {0,32,64,96,128,160, 0,8,16,24,32,40,
                              0,2,4,6,8,10,12,14,16,18,20,22,
                              0,1,2,3,4,5,6,7,8,9,10,11, 0,1,2,3,4,5};
__constant__ int jb_n[42]  = {32,32,32,32,32,32, 8,8,8,8,8,8, 2,2,2,2,2,2,2,2,2,2,2,2,
                              1,1,1,1,1,1,1,1,1,1,1,1, 1,1,1,1,1,1};

// scratch (device globals; no allocation)
__device__ __align__(16) float d_At[NM*CT*CTP];        // At[m][c][d] (stride CTP)
__device__ float  d_Spyr[NM*1364];                     // alias pyramid of s per mode
__device__ __align__(16) float2 d_Zh[NB*12288];        // per-level DFTs of z
__device__ __align__(16) float  d_V [(size_t)NB*33*KTOT]; // Gram rows (0..31 = U-hat, 32 = w-hat)
__device__ float  d_G [NB*1089];                       // Gram accumulators (atomic)

struct InPtrs { const float* z[5]; const float* w[5]; };

// ----------------------------------------------------------- f32x2 helpers
__device__ __forceinline__ unsigned long long pack2(float a){
    unsigned long long r;
    asm("mov.b64 %0, {%1, %1};" : "=l"(r) : "f"(a));
    return r;
}
__device__ __forceinline__ void ffma2(unsigned long long &d, unsigned long long a, unsigned long long b){
    asm("fma.rn.f32x2 %0, %1, %2, %0;" : "+l"(d) : "l"(a), "l"(b));
}
__device__ __forceinline__ void fadd2(unsigned long long &d, unsigned long long a){
    asm("add.rn.f32x2 %0, %1, %0;" : "+l"(d) : "l"(a));
}
__device__ __forceinline__ void fmul2(unsigned long long &d, unsigned long long a){
    asm("mul.rn.f32x2 %0, %1, %0;" : "+l"(d) : "l"(a));
}
__device__ __forceinline__ float2 unpack2(unsigned long long v){
    float2 r;
    asm("mov.b64 {%0, %1}, %2;" : "=f"(r.x), "=f"(r.y) : "l"(v));
    return r;
}

// 4d x 1k accumulate (ac0..ac3) with broadcast A float4 and one X value
#define ACC4(av, x) do { \
    ffma2(ac0, pack2((av).x), (x)); \
    ffma2(ac1, pack2((av).y), (x)); \
    ffma2(ac2, pack2((av).z), (x)); \
    ffma2(ac3, pack2((av).w), (x)); \
} while(0)

// 4d x 4k accumulate into ac[16] (d-major), X = 4 consecutive complex
#define ACC16A(av, x01, x23) do { \
    unsigned long long A0=pack2((av).x), A1=pack2((av).y); \
    unsigned long long A2=pack2((av).z), A3=pack2((av).w); \
    ffma2(ac[0], A0,(x01).x); ffma2(ac[1], A0,(x01).y); ffma2(ac[2], A0,(x23).x); ffma2(ac[3], A0,(x23).y); \
    ffma2(ac[4], A1,(x01).x); ffma2(ac[5], A1,(x01).y); ffma2(ac[6], A1,(x23).x); ffma2(ac[7], A1,(x23).y); \
    ffma2(ac[8], A2,(x01).x); ffma2(ac[9], A2,(x01).y); ffma2(ac[10],A2,(x23).x); ffma2(ac[11],A2,(x23).y); \
    ffma2(ac[12],A3,(x01).x); ffma2(ac[13],A3,(x01).y); ffma2(ac[14],A3,(x23).x); ffma2(ac[15],A3,(x23).y); \
} while(0)

// ============= fused preprocessing: prepA (blocks 0..1439), spyr (1440..1471), dft (1472..1807)
__global__ void __launch_bounds__(256) k_prep(const float* __restrict__ L,
                                              const float* __restrict__ lam,
                                              InPtrs P){
    __shared__ float sh[3136];
    int bx = blockIdx.x;
    int tid = threadIdx.x;

    if (bx < 1440){
        // ---------------- At = L^T - L, pair-tiled (32x32 pair per block)
        float (*Ta)[33] = (float(*)[33])sh;
        float (*Tb)[33] = (float(*)[33])(sh + 1056);
        int m = bx / 45, p = bx - m*45;
        int i0 = c_pbi[p]*32, j0 = c_pbj[p]*32;
        int tx = tid & 31, ty0 = tid >> 5;
        const float* Lm = L + (size_t)m*CT2;
        #pragma unroll
        for (int rr=0; rr<4; ++rr){
            int ty = ty0 + rr*8;
            int r = i0+ty, c = j0+tx;
            Ta[ty][tx] = (r<CT && c<CT) ? Lm[r*CT + c] : 0.f;
            r = j0+ty; c = i0+tx;
            Tb[ty][tx] = (r<CT && c<CT) ? Lm[r*CT + c] : 0.f;
        }
        __syncthreads();
        #pragma unroll
        for (int rr=0; rr<4; ++rr){
            int ty = ty0 + rr*8;
            if (i0+ty<CT && j0+tx<CT)
                d_At[((size_t)m*CT + i0+ty)*CTP + j0+tx] = Ta[ty][tx] - Tb[tx][ty];
            if (j0+ty<CT && i0+tx<CT)
                d_At[((size_t)m*CT + j0+ty)*CTP + i0+tx] = Tb[ty][tx] - Ta[tx][ty];
        }
    } else if (bx < 1472){
        // ---------------- s pyramid + zero d_G
        float* sA = sh;           // 1024
        float* sB = sh + 1024;    // 256
        int m = bx - 1440;
        int gidx = m*256 + tid;
        if (gidx < NB*1089) d_G[gidx] = 0.f;
        const float* lm = lam + m*1024;
        for (int t=tid; t<1024; t+=256){
            int p = t>>5, q = t&31;
            float v = lm[t] - lm[(((32-p)&31)<<5) + ((32-q)&31)];
            sA[t] = v;
            d_Spyr[m*1364 + 340 + t] = v;
        }
        float* src = sA; float* dst = sB;
        int hs = 32;
        for (int k=0; k<4; ++k){
            __syncthreads();
            int hn = hs>>1;
            int off = c_LO[3-k];        // 84,20,4,0
            for (int t=tid; t<hn*hn; t+=256){
                int p = t/hn, q = t-p*hn;
                float v = src[p*hs+q] + src[(p+hn)*hs+q]
                        + src[p*hs+q+hn] + src[(p+hn)*hs+q+hn];
                dst[t] = v;
                d_Spyr[m*1364 + off + t] = v;
            }
            float* tmp = src; src = dst; dst = tmp;
            hs = hn;
        }
    } else {
        // ---------------- batched small 2D DFTs of z (and w -> V row 32)
        float* sIn = sh;            // 1024
        float* tRe = sh + 1024;     // 1024
        float* tIm = sh + 2048;     // 1024
        float2* tw = (float2*)(sh + 3072);  // 32
        int idx = bx - 1472;
        int j = idx % 42;
        int t2 = idx / 42;
        int b = t2 & 3, isw = t2 >> 2;
        int l = jb_l[j];
        int h = c_h[l], hm = h-1;
        int lh = 31 - __clz(h);
        int lh2 = 2*lh;
        int h2 = h*h;
        int c0 = jb_c0[j], nch = jb_n[j];
        int npts = nch*h2;
        const float* in = (isw ? P.w[l] : P.z[l]) + (size_t)(b*c_cnt[l] + c0)*h2;
        if (tid < h){
            float sn, cn; __sincosf(-6.283185307179586f*(float)tid/(float)h, &sn, &cn);
            tw[tid] = make_float2(cn, sn);
        }
        for (int t=tid; t<npts; t+=256) sIn[t] = in[t];
        __syncthreads();
        for (int t=tid; t<npts; t+=256){
            int ch = t>>lh2;
            int pt = t & (h2-1);
            int p = pt>>lh, x = pt&hm;
            const float* base = sIn + (ch<<lh2) + x;
            float ar=0.f, ai=0.f;
            for (int y=0; y<h; ++y){
                float2 e = tw[(p*y)&hm];
                float v = base[y<<lh];
                ar += v*e.x; ai += v*e.y;
            }
            tRe[t]=ar; tIm[t]=ai;
        }
        __syncthreads();
        float inv = 1.0f/(float)h;
        float* vrow = d_V + ((size_t)(b*33+32))*KTOT;
        for (int t=tid; t<npts; t+=256){
            int ch = t>>lh2;
            int pt = t & (h2-1);
            int p = pt>>lh, q = pt&hm;
            const float* bR = tRe + (ch<<lh2) + (p<<lh);
            const float* bI = tIm + (ch<<lh2) + (p<<lh);
            float ar=0.f, ai=0.f;
            for (int x=0; x<h; ++x){
                float2 e = tw[(q*x)&hm];
                float re = bR[x], im = bI[x];
                ar += re*e.x - im*e.y;
                ai += re*e.y + im*e.x;
            }
            int kk = c_OffC[l] + (c0<<lh2) + t;
            if (!isw){
                d_Zh[b*12288 + kk] = make_float2(ar, ai);
            } else {
                vrow[2*kk  ] =  ai*inv;
                vrow[2*kk+1] = -ar*inv;
            }
        }
    }
}

// 4-point downward alias within compact pyramid (smem)
__device__ __forceinline__ void alias_down(float2* __restrict__ sXp2,
                                           int lc, int lt, int ch, int pt){
    int ht = c_h[lt], hsrc = ht*2;
    int p = pt / ht, q = pt - p*ht;
    float2* base = sXp2 + c_LB2[lc] + ch*c_PS2[lc];
    const float2* src = base + c_LO[lt+1];
    float2 a0=src[p*hsrc+q],        a1=src[(p+ht)*hsrc+q];
    float2 a2=src[p*hsrc+q+ht],     a3=src[(p+ht)*hsrc+q+ht];
    base[c_LO[lt]+pt] = make_float2(a0.x+a1.x+a2.x+a3.x, a0.y+a1.y+a2.y+a3.y);
}

// ====================== fused per-(b,m) vector-field kernel ======================
__global__ void __launch_bounds__(NTH) k_main(){
    extern __shared__ float smraw[];
    float2* sXp2 = (float2*)smraw;             // [SXP2_N]
    float2* sC   = sXp2 + SXP2_N;              // [SC_N]
    float*  sS   = (float*)(sC + SC_N);        // [1364]
    float*  sU   = sS + 1364;                  // [1536] level-0 accumulators
    int m = blockIdx.x, b = blockIdx.y;
    int tid = threadIdx.x;
    int wid = tid >> 5, lane = tid & 31;

    for (int t=tid; t<1364; t+=NTH) sS[t] = d_Spyr[m*1364 + t];
    for (int t=tid; t<1536; t+=NTH) sU[t] = 0.f;
    for (int t=tid; t<720;  t+=NTH) ((float*)sC)[t] = 0.f;   // ls=0 C region (atomic)
    __syncthreads();

    const float2* Zb = d_Zh + b*12288;
    const float*  Atm = d_At + (size_t)m*CT*CTP;

    // ---- phase 1A: top stored slice per channel (4-pt alias from global Z x S)
    for (int t=tid; t<2880; t+=NTH){
        int lc, ch, pt;
        if (t<192){lc=1; ch=t>>2; pt=t&3;}
        else if (t<576){lc=2; int u=t-192; ch=u>>4; pt=u&15;}
        else if (t<1344){lc=3; int u=t-576; ch=u>>6; pt=u&63;}
        else {lc=4; int u=t-1344; ch=u>>8; pt=u&255;}
        int ht = c_h[lc-1], hs = ht*2;
        int p = pt / ht, q = pt - p*ht;
        const float* Sl = sS + c_LO[lc];
        const float2* Zc = Zb + c_OffC[lc] + ch*hs*hs;
        float ar=0.f, ai=0.f;
        #pragma unroll
        for (int i=0;i<2;++i){
            #pragma unroll
            for (int jj=0;jj<2;++jj){
                int idx = (p+i*ht)*hs + (q+jj*ht);
                float s = Sl[idx];
                float2 z = Zc[idx];
                ar += s*z.x; ai += s*z.y;
            }
        }
        sXp2[c_LB2[lc] + ch*c_PS2[lc] + c_LO[lc-1] + pt] = make_float2(ar, ai);
    }
    __syncthreads();

    // ---- phase 1B: downward aliasing within smem (3 rounds)
    for (int t=tid; t<672; t+=NTH){
        if (t<96)       alias_down(sXp2, 2, 0, t>>2, t&3);
        else if (t<288){int u=t-96;  alias_down(sXp2, 3, 1, u>>4, u&15);}
        else           {int u=t-288; alias_down(sXp2, 4, 2, u>>6, u&63);}
    }
    __syncthreads();
    for (int t=tid; t<144; t+=NTH){
        if (t<48)      alias_down(sXp2, 3, 0, t>>2, t&3);
        else          {int u=t-48; alias_down(sXp2, 4, 1, u>>4, u&15);}
    }
    __syncthreads();
    for (int t=tid; t<24; t+=NTH) alias_down(sXp2, 4, 0, t>>2, t&3);
    __syncthreads();

    // ---- phase 2: C table, warp-cooperative (63 warp-items)
    for (int it = wid; it < 63; it += NW){
        if (it < 12){
            // ls0: lane = d (32 per group, 3 groups: 0..95, valid <90), 4 residues in regs
            int g = it >> 2, cc = it & 3;
            int di = g*32 + lane;
            bool ok = di < 90;
            int diL = ok ? di : 89;
            int clo = cc*48, chi = clo+48;
            unsigned long long a0=0ull,a1=0ull,a2=0ull,a3=0ull;
            const float* ap = Atm + (size_t)clo*CTP + 192 + diL;
            const ulonglong2* zp = (const ulonglong2*)((const unsigned long long*)Zb + clo*4);
            for (int c=clo; c<chi; ++c){
                unsigned long long av = pack2(__ldg(ap));
                ulonglong2 z01 = zp[0];
                ulonglong2 z23 = zp[1];
                ffma2(a0,av,z01.x); ffma2(a1,av,z01.y);
                ffma2(a2,av,z23.x); ffma2(a3,av,z23.y);
                ap += CTP; zp += 2;
            }
            if (ok){
                float* f = (float*)sC + di*8;
                float2 v;
                v=unpack2(a0); atomicAdd(f+0,v.x); atomicAdd(f+1,v.y);
                v=unpack2(a1); atomicAdd(f+2,v.x); atomicAdd(f+3,v.y);
                v=unpack2(a2); atomicAdd(f+4,v.x); atomicAdd(f+5,v.y);
                v=unpack2(a3); atomicAdd(f+6,v.x); atomicAdd(f+7,v.y);
            }
        } else if (it < 33){                 // ls1: 21 items, 2 di x 16 r
            int ii = it - 12;
            int di = ii*2 + (lane>>4);       // 0..41
            int r  = lane & 15;
            unsigned long long acc = 0ull;
            const float* ap = Atm + (size_t)192*CTP + 240 + di;
            const unsigned long long* zp = (const unsigned long long*)(Zb + 768) + r;
            for (int c=0;c<48;++c){
                ffma2(acc, pack2(__ldg(ap)), zp[(size_t)c*16]);
                ap += CTP;
            }
            ((unsigned long long*)sC)[360 + di*16 + r] = acc;
        } else if (it < 51){                 // ls2: 18 items, 1 di x 64 r (2/lane)
            int di = it - 33;
            int r0 = lane*2;
            unsigned long long a0=0ull, a1=0ull;
            const float* ap = Atm + (size_t)240*CTP + 264 + di;
            const ulonglong2* zp = (const ulonglong2*)(Zb + 1536 + r0);
            for (int c=0;c<24;++c){
                unsigned long long av = pack2(__ldg(ap));
                ulonglong2 z = zp[(size_t)c*32];
                ffma2(a0, av, z.x); ffma2(a1, av, z.y);
                ap += CTP;
            }
            unsigned long long* Cu = (unsigned long long*)sC + 1032 + di*64 + r0;
            Cu[0]=a0; Cu[1]=a1;
        } else {                             // ls3: 12 items, (di, kt), 4 r/lane
            int u = it - 51;
            int di = u >> 1, kt = u & 1;
            int r0 = kt*128 + lane*4;
            unsigned long long a0=0ull,a1=0ull,a2=0ull,a3=0ull;
            const float* ap = Atm + (size_t)264*CTP + 276 + di;
            const ulonglong2* zp = (const ulonglong2*)(Zb + 3072 + r0);
            for (int c=0;c<12;++c){
                unsigned long long av = pack2(__ldg(ap));
                ulonglong2 z01 = zp[(size_t)c*128];
                ulonglong2 z23 = zp[(size_t)c*128 + 1];
                ffma2(a0,av,z01.x); ffma2(a1,av,z01.y);
                ffma2(a2,av,z23.x); ffma2(a3,av,z23.y);
                ap += CTP;
            }
            unsigned long long* Cu = (unsigned long long*)sC + 2184 + di*256 + r0;
            Cu[0]=a0; Cu[1]=a1; Cu[2]=a2; Cu[3]=a3;
        }
    }
    __syncthreads();

    // ---- phase 3: mixing, warp-cooperative (46 warp-items, 2-round snake schedule)
    float* vbase = d_V + ((size_t)(b*33+m))*KTOT;
    const unsigned long long* Cb0 = (const unsigned long long*)sC;
    for (int s = wid; s < 48; s += NW){
        int it = c_perm[s];
        if (it < 0) continue;

        if (it < 12){
            // l0: lane = d (32 per group, 6 groups), 4 k in regs; 2 channel-chunks
            int g = it >> 1, chunk = it & 1;
            int d = g*32 + lane;
            unsigned long long ac0=0ull,ac1=0ull,ac2=0ull,ac3=0ull;
            int clo = chunk ? 141 : 0;
            int ce  = chunk ? 192 : 141;
            {
                const float* ap = Atm + (size_t)clo*CTP + d;
                const ulonglong2* zp = (const ulonglong2*)((const unsigned long long*)Zb + clo*4);
                for (int c=clo; c<ce; ++c){
                    unsigned long long av = pack2(__ldg(ap));
                    ulonglong2 x01 = zp[0];
                    ulonglong2 x23 = zp[1];
                    ffma2(ac0,av,x01.x); ffma2(ac1,av,x01.y);
                    ffma2(ac2,av,x23.x); ffma2(ac3,av,x23.y);
                    ap += CTP; zp += 2;
                }
                fmul2(ac0, pack2(sS[0])); fmul2(ac1, pack2(sS[1]));
                fmul2(ac2, pack2(sS[2])); fmul2(ac3, pack2(sS[3]));
            }
            if (chunk){
                for (int lc=1; lc<5; ++lc){
                    int cb=c_cbase[lc], ce2=c_cbase[lc+1];
                    int ps2 = c_PS2[lc] >> 1;    // stride in ulonglong2 units
                    const ulonglong2* xp = (const ulonglong2*)(sXp2 + c_LB2[lc]);
                    const float* ap = Atm + (size_t)cb*CTP + d;
                    for (int c=cb;c<ce2;++c){
                        unsigned long long av = pack2(__ldg(ap));
                        ulonglong2 x01 = xp[0];
                        ulonglong2 x23 = xp[1];
                        ffma2(ac0,av,x01.x); ffma2(ac1,av,x01.y);
                        ffma2(ac2,av,x23.x); ffma2(ac3,av,x23.y);
                        ap += CTP; xp += ps2;
                    }
                }
            }
            float* u = sU + d*8;
            float2 v;
            v=unpack2(ac0); atomicAdd(u+0,v.x); atomicAdd(u+1,v.y);
            v=unpack2(ac1); atomicAdd(u+2,v.x); atomicAdd(u+3,v.y);
            v=unpack2(ac2); atomicAdd(u+4,v.x); atomicAdd(u+5,v.y);
            v=unpack2(ac3); atomicAdd(u+6,v.x); atomicAdd(u+7,v.y);
        } else if (it < 18){
            // l1: 8 d x 16 k; lanes = (dl in 2, k in 16)
            int ii = it - 12;
            int dl = lane >> 4;
            int k  = lane & 15;
            int d0 = 192 + ii*8 + dl*4;
            int p = k>>2, q = k&3;
            int r = (p&1)*2 + (q&1);
            unsigned long long ac0 = Cb0[(d0-192)*4 + r];
            unsigned long long ac1 = Cb0[(d0-191)*4 + r];
            unsigned long long ac2 = Cb0[(d0-190)*4 + r];
            unsigned long long ac3 = Cb0[(d0-189)*4 + r];
            {
                const float* ap = Atm + (size_t)192*CTP + d0;
                const unsigned long long* zp = (const unsigned long long*)(Zb + 768) + k;
                for (int c=0;c<48;++c){
                    float4 av = __ldg((const float4*)ap);
                    unsigned long long x = zp[(size_t)c*16];
                    ACC4(av, x);
                    ap += CTP;
                }
                unsigned long long s2 = pack2(sS[4+k]);
                fmul2(ac0,s2); fmul2(ac1,s2); fmul2(ac2,s2); fmul2(ac3,s2);
            }
            for (int lc=2; lc<5; ++lc){
                int cb=c_cbase[lc], ce2=c_cbase[lc+1];
                int ps=c_PS2[lc];
                const unsigned long long* xp = (const unsigned long long*)(sXp2 + c_LB2[lc]) + 4 + k;
                const float* ap = Atm + (size_t)cb*CTP + d0;
                for (int c=cb;c<ce2;++c){
                    float4 av = __ldg((const float4*)ap);
                    unsigned long long x = *xp;
                    ACC4(av, x);
                    ap += CTP; xp += ps;
                }
            }
            const float sc = 4.0f/1024.0f;
            float* vp = vbase + 2*(768 + (d0-192)*16 + k);
            float2 v;
            v=unpack2(ac0); vp[0]=sc*v.x;  vp[1]=sc*v.y;
            v=unpack2(ac1); vp[32]=sc*v.x; vp[33]=sc*v.y;
            v=unpack2(ac2); vp[64]=sc*v.x; vp[65]=sc*v.y;
            v=unpack2(ac3); vp[96]=sc*v.x; vp[97]=sc*v.y;
        } else if (it < 24){
            // l2: 4 d x 64 k; lanes = 2 k each
            int dg = it - 18;
            int d0 = 240 + dg*4;
            int k0 = lane*2;
            unsigned long long ac[8];
            #pragma unroll
            for (int j=0;j<2;++j){
                int k = k0+j;
                int p=k>>3, q=k&7;
                int r0=(p&1)*2+(q&1), r1=(p&3)*4+(q&3);
                #pragma unroll
                for (int dj=0;dj<4;++dj){
                    unsigned long long a = Cb0[(d0-192+dj)*4 + r0];
                    fadd2(a, Cb0[360 + (d0-240+dj)*16 + r1]);
                    ac[dj*2+j] = a;
                }
            }
            {
                const float* ap = Atm + (size_t)240*CTP + d0;
                const ulonglong2* zp = (const ulonglong2*)(Zb + 1536 + k0);
                for (int c=0;c<24;++c){
                    float4 av = __ldg((const float4*)ap);
                    ulonglong2 x = zp[(size_t)c*32];
                    unsigned long long A0=pack2(av.x),A1=pack2(av.y),A2=pack2(av.z),A3=pack2(av.w);
                    ffma2(ac[0],A0,x.x); ffma2(ac[1],A0,x.y);
                    ffma2(ac[2],A1,x.x); ffma2(ac[3],A1,x.y);
                    ffma2(ac[4],A2,x.x); ffma2(ac[5],A2,x.y);
                    ffma2(ac[6],A3,x.x); ffma2(ac[7],A3,x.y);
                    ap += CTP;
                }
                unsigned long long s0 = pack2(sS[20+k0]);
                unsigned long long s1 = pack2(sS[21+k0]);
                fmul2(ac[0],s0); fmul2(ac[1],s1);
                fmul2(ac[2],s0); fmul2(ac[3],s1);
                fmul2(ac[4],s0); fmul2(ac[5],s1);
                fmul2(ac[6],s0); fmul2(ac[7],s1);
            }
            for (int lc=3; lc<5; ++lc){
                int cb=c_cbase[lc], ce2=c_cbase[lc+1];
                int ps2 = c_PS2[lc]>>1;
                const ulonglong2* xp = (const ulonglong2*)(sXp2 + c_LB2[lc] + 20 + k0);
                const float* ap = Atm + (size_t)cb*CTP + d0;
                for (int c=cb;c<ce2;++c){
                    float4 av = __ldg((const float4*)ap);
                    ulonglong2 x = *xp;
                    unsigned long long A0=pack2(av.x),A1=pack2(av.y),A2=pack2(av.z),A3=pack2(av.w);
                    ffma2(ac[0],A0,x.x); ffma2(ac[1],A0,x.y);
                    ffma2(ac[2],A1,x.x); ffma2(ac[3],A1,x.y);
                    ffma2(ac[4],A2,x.x); ffma2(ac[5],A2,x.y);
                    ffma2(ac[6],A3,x.x); ffma2(ac[7],A3,x.y);
                    ap += CTP; xp += ps2;
                }
            }
            const float sc = 8.0f/1024.0f;
            #pragma unroll
            for (int dj=0;dj<4;++dj){
                float* vp = vbase + 2*(1536 + (d0-240+dj)*64 + k0);
                float2 va=unpack2(ac[dj*2]), vb=unpack2(ac[dj*2+1]);
                *(float4*)vp = make_float4(sc*va.x, sc*va.y, sc*vb.x, sc*vb.y);
            }
        } else if (it < 30){
            // l3: 4 d x 128 k; lanes = 4 k each
            int u = it - 24;
            int dg = u >> 1, kt = u & 1;
            int d0 = 264 + dg*4;
            int k0 = kt*128 + lane*4;
            unsigned long long ac[16];
            int p = k0 >> 4, q0 = k0 & 15;
            #pragma unroll
            for (int j=0;j<4;++j){
                int q = q0 + j;
                int r0=(p&1)*2+(q&1), r1=(p&3)*4+(q&3), r2=(p&7)*8+(q&7);
                #pragma unroll
                for (int dj=0;dj<4;++dj){
                    unsigned long long a = Cb0[(d0-192+dj)*4 + r0];
                    fadd2(a, Cb0[360 + (d0-240+dj)*16 + r1]);
                    fadd2(a, Cb0[1032 + (d0-264+dj)*64 + r2]);
                    ac[dj*4+j] = a;
                }
            }
            {
                const float* ap = Atm + (size_t)264*CTP + d0;
                const ulonglong2* zp = (const ulonglong2*)(Zb + 3072 + k0);
                for (int c=0;c<12;++c){
                    float4 av = __ldg((const float4*)ap);
                    ulonglong2 x01 = zp[(size_t)c*128];
                    ulonglong2 x23 = zp[(size_t)c*128 + 1];
                    ACC16A(av, x01, x23);
                    ap += CTP;
                }
                #pragma unroll
                for (int j=0;j<4;++j){
                    unsigned long long s2 = pack2(sS[84 + k0 + j]);
                    fmul2(ac[j],s2); fmul2(ac[4+j],s2); fmul2(ac[8+j],s2); fmul2(ac[12+j],s2);
                }
            }
            {
                const ulonglong2* xp = (const ulonglong2*)(sXp2 + 1680 + 84 + k0);
                const float* ap = Atm + (size_t)276*CTP + d0;
                for (int c=0;c<6;++c){
                    float4 av = __ldg((const float4*)ap);
                    ulonglong2 x01 = xp[0];
                    ulonglong2 x23 = xp[1];
                    ACC16A(av, x01, x23);
                    ap += CTP; xp += 170;
                }
            }
            const float sc = 16.0f/1024.0f;
            #pragma unroll
            for (int dj=0;dj<4;++dj){
                float* vp = vbase + 2*(3072 + (d0-264+dj)*256 + k0);
                float2 v0=unpack2(ac[dj*4+0]), v1=unpack2(ac[dj*4+1]);
                float2 v2=unpack2(ac[dj*4+2]), v3=unpack2(ac[dj*4+3]);
                *(float4*)vp     = make_float4(sc*v0.x, sc*v0.y, sc*v1.x, sc*v1.y);
                *(float4*)(vp+4) = make_float4(sc*v2.x, sc*v2.y, sc*v3.x, sc*v3.y);
            }
        } else {
            // l4: up to 4 d x 128 k; lanes = 4 k each
            int u = it - 30;
            int dg = u >> 3, kt = u & 7;
            int d0 = 276 + dg*4;
            int dcnt = 282 - d0; if (dcnt>4) dcnt=4;
            int k0 = kt*128 + lane*4;
            unsigned long long ac[16];
            int p = k0 >> 5, q0 = k0 & 31;
            #pragma unroll
            for (int j=0;j<4;++j){
                int q = q0 + j;
                int r0=(p&1)*2+(q&1), r1=(p&3)*4+(q&3);
                int r2=(p&7)*8+(q&7), r3=(p&15)*16+(q&15);
                #pragma unroll
                for (int dj=0;dj<4;++dj){
                    unsigned long long a = Cb0[(d0-192+dj)*4 + r0];
                    fadd2(a, Cb0[360 + (d0-240+dj)*16 + r1]);
                    fadd2(a, Cb0[1032 + (d0-264+dj)*64 + r2]);
                    fadd2(a, Cb0[2184 + (d0-276+dj)*256 + r3]);
                    ac[dj*4+j] = a;
                }
            }
            {
                const float* ap = Atm + (size_t)276*CTP + d0;
                const ulonglong2* zp = (const ulonglong2*)(Zb + 6144 + k0);
                for (int c=0;c<6;++c){
                    float4 av = __ldg((const float4*)ap);
                    ulonglong2 x01 = zp[(size_t)c*512];
                    ulonglong2 x23 = zp[(size_t)c*512 + 1];
                    ACC16A(av, x01, x23);
                    ap += CTP;
                }
                #pragma unroll
                for (int j=0;j<4;++j){
                    unsigned long long s2 = pack2(sS[340 + k0 + j]);
                    fmul2(ac[j],s2); fmul2(ac[4+j],s2); fmul2(ac[8+j],s2); fmul2(ac[12+j],s2);
                }
            }
            const float sc = 32.0f/1024.0f;
            for (int dj=0;dj<dcnt;++dj){
                float* vp = vbase + 2*(6144 + (d0-276+dj)*1024 + k0);
                float2 v0=unpack2(ac[dj*4+0]), v1=unpack2(ac[dj*4+1]);
                float2 v2=unpack2(ac[dj*4+2]), v3=unpack2(ac[dj*4+3]);
                *(float4*)vp     = make_float4(sc*v0.x, sc*v0.y, sc*v1.x, sc*v1.y);
                *(float4*)(vp+4) = make_float4(sc*v2.x, sc*v2.y, sc*v3.x, sc*v3.y);
            }
        }
    }
    __syncthreads();

    // ---- phase 3d: write out level 0 from sU
    for (int t=tid; t<1536; t+=NTH)
        vbase[t] = (2.0f/1024.0f) * sU[t];
}

// ------------------------------------------------- segmented 33x33 Gram -> atomic d_G
#define GSTR 260
__global__ void __launch_bounds__(256) k_gram(){
    __shared__ __align__(16) float sm[34*GSTR];
    int seg = blockIdx.x, b = blockIdx.y;
    int tid = threadIdx.x;          // 256
    const float* Vb = d_V + (size_t)b*33*KTOT + seg*SEG;
    for (int r=0; r<33; ++r) sm[r*GSTR+tid] = Vb[(size_t)r*KTOT + tid];
    sm[33*GSTR+tid] = 0.f;
    __syncthreads();
    float* gG = d_G + b*1089;
    if (tid < 153){
        int t = tid;
        int ti = (int)((35.0f - sqrtf(1225.0f - 8.0f*(float)t)) * 0.5f);
        if (ti > 16) ti = 16; if (ti < 0) ti = 0;
        int off = 17*ti - (ti*(ti-1))/2;
        while (off > t){ ti--; off = 17*ti - (ti*(ti-1))/2; }
        while (off + (17-ti) <= t){ off += 17-ti; ti++; }
        int tj = ti + (t - off);
        const float* r0 = sm + (2*ti)*GSTR;
        const float* r1 = r0 + GSTR;
        const float* q0 = sm + (2*tj)*GSTR;
        const float* q1 = q0 + GSTR;
        float a00=0,a01=0,a10=0,a11=0;
        for (int k=0; k<SEG; k+=4){
            float4 x0 = *(const float4*)(r0+k);
            float4 x1 = *(const float4*)(r1+k);
            float4 y0 = *(const float4*)(q0+k);
            float4 y1 = *(const float4*)(q1+k);
            a00 += x0.x*y0.x + x0.y*y0.y + x0.z*y0.z + x0.w*y0.w;
            a01 += x0.x*y1.x + x0.y*y1.y + x0.z*y1.z + x0.w*y1.w;
            a10 += x1.x*y0.x + x1.y*y0.y + x1.z*y0.z + x1.w*y0.w;
            a11 += x1.x*y1.x + x1.y*y1.y + x1.z*y1.z + x1.w*y1.w;
        }
        int i0=2*ti, j0=2*tj;
        int i1=i0+1, j1=j0+1;
        atomicAdd(gG + i0*33+j0, a00);
        if (j1<33) atomicAdd(gG + i0*33+j1, a01);
        if (i1<33) atomicAdd(gG + i1*33+j0, a10);
        if (i1<33 && j1<33) atomicAdd(gG + i1*33+j1, a11);
        if (ti != tj){
            atomicAdd(gG + j0*33+i0, a00);
            if (j1<33) atomicAdd(gG + j1*33+i0, a01);
            if (i1<33) atomicAdd(gG + j0*33+i1, a10);
            if (i1<33 && j1<33) atomicAdd(gG + j1*33+i1, a11);
        }
    }
}

// ------------------------------------------------- stats + warp-register Cholesky + logdet
__global__ void k_final(float* __restrict__ out){
    __shared__ float G[1089];
    __shared__ float sc0;
    int b = blockIdx.x;
    int tid = threadIdx.x;          // 256
    for (int pair=tid; pair<1089; pair+=256) G[pair] = d_G[b*1089 + pair];
    __syncthreads();
    if (tid < 32){
        float dg = G[tid*33+tid];
        for (int o=16;o>0;o>>=1) dg += __shfl_down_sync(0xffffffffu, dg, o);
        if (tid==0){
            float var = dg * (1.0f/32.0f);
            if (var < 1e-6f) var = 1e-6f;
            sc0 = var;
        }
    }
    __syncthreads();
    float var = sc0;
    float inv_var = 1.0f/var;

    if (tid < 32){
        int i = tid;
        // lane i holds row i of M in registers (static indices via full unroll)
        float r[32];
        #pragma unroll
        for (int j=0;j<32;++j)
            r[j] = G[i*33+j]*inv_var + ((i==j)?EPSR:0.f);

        float diag = 1.0f;
        #pragma unroll
        for (int k=0;k<32;++k){
            float dkk = __shfl_sync(0xffffffffu, r[k], k);
            float s   = sqrtf(dkk);
            float inv = 1.0f/s;
            if (i == k){ r[k] = s; diag = s; }
            else if (i > k) r[k] *= inv;
            // trailing update: M[i][j] -= L[i][k]*L[j][k], j = k+1..31
            #pragma unroll
            for (int j=k+1;j<32;++j){
                float ljk = __shfl_sync(0xffffffffu, r[k], j);
                if (i >= j) r[j] -= r[k]*ljk;
            }
        }

        float ld  = 2.0f*logf(diag);
        float zw  = G[i*33+32];
        float zw2 = zw*zw;
        for (int o=16;o>0;o>>=1){
            ld  += __shfl_down_sync(0xffffffffu, ld,  o);
            zw2 += __shfl_down_sync(0xffffffffu, zw2, o);
        }
        if (i==0){
            float trace = EPSR*G[32*33+32] + zw2*inv_var;
            out[b] = 0.5f*(ld - trace);
        }
    }
}

// ----------------------------------------------------------------------------
extern "C" void kernel_launch(void* const* d_in, const int* in_sizes, int n_in,
                              void* d_out, int out_size){
    (void)n_in; (void)out_size;
    InPtrs P;
    const float* L; const float* lam;
    if (in_sizes[0] > 1000000){
        // alphabetical: L, lam, w0..w4, z0..z4
        L   = (const float*)d_in[0];
        lam = (const float*)d_in[1];
        for (int l=0;l<5;++l){ P.w[l] = (const float*)d_in[2+l]; P.z[l] = (const float*)d_in[7+l]; }
    } else if (in_sizes[2] == 6144){
        // grouped: z0..z4, w0..w4, L, lam
        for (int l=0;l<5;++l){ P.z[l] = (const float*)d_in[l]; P.w[l] = (const float*)d_in[5+l]; }
        L   = (const float*)d_in[10];
        lam = (const float*)d_in[11];
    } else {
        // dict insertion order: z0,w0,z1,w1,...,L,lam
        for (int l=0;l<5;++l){ P.z[l] = (const float*)d_in[2*l]; P.w[l] = (const float*)d_in[2*l+1]; }
        L   = (const float*)d_in[10];
        lam = (const float*)d_in[11];
    }
    float* out = (float*)d_out;

    static int smem_set = 0;
    if (!smem_set){
        cudaFuncSetAttribute(k_main, cudaFuncAttributeMaxDynamicSharedMemorySize, SMEM_MAIN);
        smem_set = 1;
    }

    k_prep<<<1808, 256>>>(L, lam, P);
    k_main<<<dim3(NM, NB), NTH, SMEM_MAIN>>>();
    k_gram<<<dim3(NSEG, NB), 256>>>();
    k_final<<<NB, 256>>>(out);
}